// round 1
// baseline (speedup 1.0000x reference)
#include <cuda_runtime.h>
#include <math.h>

// Problem constants
#define Bsz 2
#define Sq 2048
#define Dm 1024
#define Hh 16
#define DHd 64
#define Ff 4096
#define NTOK (Bsz*Sq)   // 4096 tokens

// ---------------- scratch (device globals; no runtime allocation) -------------
__device__ float g_x[(size_t)NTOK*Dm];
__device__ float g_q[(size_t)NTOK*Dm];
__device__ float g_k[(size_t)NTOK*Dm];
__device__ float g_v[(size_t)NTOK*Dm];
__device__ float g_attn[(size_t)NTOK*Dm];
__device__ float g_proj[(size_t)NTOK*Dm];
__device__ float g_a[(size_t)NTOK*Dm];
__device__ float g_h1[(size_t)NTOK*Ff];
__device__ float g_ffn[(size_t)NTOK*Dm];

// ---------------- elementwise add: x = x_enc + x_pos --------------------------
__global__ __launch_bounds__(256) void add_kernel(const float* __restrict__ a,
                                                  const float* __restrict__ b,
                                                  float* __restrict__ o, int n4)
{
    int i = blockIdx.x * blockDim.x + threadIdx.x;
    if (i < n4) {
        float4 av = ((const float4*)a)[i];
        float4 bv = ((const float4*)b)[i];
        float4 ov;
        ov.x = av.x + bv.x; ov.y = av.y + bv.y;
        ov.z = av.z + bv.z; ov.w = av.w + bv.w;
        ((float4*)o)[i] = ov;
    }
}

// ---------------- SGEMM: C[M,N] = A[M,K] @ B[K,N] + bias, optional ReLU -------
// 128x128 block tile, BK=16, 256 threads, 8x8 register micro-tile.
#define GBM 128
#define GBN 128
#define GBK 16

__global__ __launch_bounds__(256) void gemm_bias_kernel(
    const float* __restrict__ A, const float* __restrict__ Bw,
    const float* __restrict__ bias, float* __restrict__ C,
    int M, int N, int K, int relu)
{
    __shared__ __align__(16) float As[GBK][132];   // padded, transposed A tile
    __shared__ __align__(16) float Bs[GBK][GBN];

    const int tid = threadIdx.x;
    const int tx = tid & 15;   // 0..15 over N
    const int ty = tid >> 4;   // 0..15 over M
    const int rowBase = blockIdx.y * GBM;
    const int colBase = blockIdx.x * GBN;

    float acc[8][8];
    #pragma unroll
    for (int i = 0; i < 8; i++)
        #pragma unroll
        for (int j = 0; j < 8; j++) acc[i][j] = 0.f;

    for (int k0 = 0; k0 < K; k0 += GBK) {
        // Load A tile 128x16 (transposed into As) and B tile 16x128.
        #pragma unroll
        for (int t = 0; t < 2; t++) {
            int id = tid + t * 256;
            int ar = id >> 2, ac4 = id & 3;
            float4 av = *(const float4*)(A + (size_t)(rowBase + ar) * K + k0 + ac4 * 4);
            As[ac4 * 4 + 0][ar] = av.x;
            As[ac4 * 4 + 1][ar] = av.y;
            As[ac4 * 4 + 2][ar] = av.z;
            As[ac4 * 4 + 3][ar] = av.w;
            int br = id >> 5, bc4 = id & 31;
            *(float4*)&Bs[br][bc4 * 4] =
                *(const float4*)(Bw + (size_t)(k0 + br) * N + colBase + bc4 * 4);
        }
        __syncthreads();

        #pragma unroll
        for (int k = 0; k < GBK; k++) {
            float4 a0 = *(float4*)&As[k][ty * 8];
            float4 a1 = *(float4*)&As[k][ty * 8 + 4];
            float4 b0 = *(float4*)&Bs[k][tx * 8];
            float4 b1 = *(float4*)&Bs[k][tx * 8 + 4];
            float ra[8] = {a0.x, a0.y, a0.z, a0.w, a1.x, a1.y, a1.z, a1.w};
            float rb[8] = {b0.x, b0.y, b0.z, b0.w, b1.x, b1.y, b1.z, b1.w};
            #pragma unroll
            for (int i = 0; i < 8; i++)
                #pragma unroll
                for (int j = 0; j < 8; j++)
                    acc[i][j] += ra[i] * rb[j];
        }
        __syncthreads();
    }

    #pragma unroll
    for (int i = 0; i < 8; i++) {
        size_t r = (size_t)(rowBase + ty * 8 + i);
        #pragma unroll
        for (int j = 0; j < 8; j += 4) {
            int c = colBase + tx * 8 + j;
            float4 bb = *(const float4*)(bias + c);
            float4 v;
            v.x = acc[i][j + 0] + bb.x;
            v.y = acc[i][j + 1] + bb.y;
            v.z = acc[i][j + 2] + bb.z;
            v.w = acc[i][j + 3] + bb.w;
            if (relu) {
                v.x = fmaxf(v.x, 0.f); v.y = fmaxf(v.y, 0.f);
                v.z = fmaxf(v.z, 0.f); v.w = fmaxf(v.w, 0.f);
            }
            *(float4*)(C + r * N + c) = v;
        }
    }
}

// ---------------- Flash attention (fp32, online softmax) ----------------------
// grid: (Sq/64, B*H). 256 threads as 16x16. 64 q-rows x 64 kv-tile, DH=64.
// smem: Qt[d][r], Kt[d][r] (transposed, stride 68), Vs[r][d], Ps[r][c].
#define AT_STRIDE 68
#define AT_SMEM (4 * 64 * AT_STRIDE * 4)

__global__ __launch_bounds__(256) void flash_attn_kernel(
    const float* __restrict__ Q, const float* __restrict__ K,
    const float* __restrict__ V, float* __restrict__ O)
{
    extern __shared__ float sm[];
    float* Qt = sm;                        // 64 x 68
    float* Kt = sm + 64 * AT_STRIDE;       // 64 x 68
    float* Vs = sm + 2 * 64 * AT_STRIDE;   // 64 x 68
    float* Ps = sm + 3 * 64 * AT_STRIDE;   // 64 x 68

    const int tid = threadIdx.x;
    const int tx = tid & 15;   // key-col group / out-dim group
    const int ty = tid >> 4;   // q-row group
    const int bh = blockIdx.y;
    const int b = bh >> 4, h = bh & 15;
    const int q0 = blockIdx.x * 64;

    const float* Qb = Q + (size_t)b * Sq * Dm + h * DHd;
    const float* Kb = K + (size_t)b * Sq * Dm + h * DHd;
    const float* Vb = V + (size_t)b * Sq * Dm + h * DHd;
    float*       Ob = O + (size_t)b * Sq * Dm + h * DHd;

    // Load Q tile transposed: Qt[d][r]
    #pragma unroll
    for (int t = 0; t < 4; t++) {
        int id = tid + t * 256;
        int r = id >> 4, c4 = id & 15;
        float4 v = *(const float4*)(Qb + (size_t)(q0 + r) * Dm + c4 * 4);
        Qt[(c4 * 4 + 0) * AT_STRIDE + r] = v.x;
        Qt[(c4 * 4 + 1) * AT_STRIDE + r] = v.y;
        Qt[(c4 * 4 + 2) * AT_STRIDE + r] = v.z;
        Qt[(c4 * 4 + 3) * AT_STRIDE + r] = v.w;
    }

    float o[4][4];
    float m[4], l[4];
    #pragma unroll
    for (int a = 0; a < 4; a++) {
        m[a] = -1e30f; l[a] = 0.f;
        #pragma unroll
        for (int d = 0; d < 4; d++) o[a][d] = 0.f;
    }
    const float scale = 0.125f;  // 1/sqrt(64)

    for (int j0 = 0; j0 < Sq; j0 += 64) {
        __syncthreads();   // previous iter's Ps/Vs reads done
        // Load K (transposed) and V tiles
        #pragma unroll
        for (int t = 0; t < 4; t++) {
            int id = tid + t * 256;
            int r = id >> 4, c4 = id & 15;
            float4 kv = *(const float4*)(Kb + (size_t)(j0 + r) * Dm + c4 * 4);
            Kt[(c4 * 4 + 0) * AT_STRIDE + r] = kv.x;
            Kt[(c4 * 4 + 1) * AT_STRIDE + r] = kv.y;
            Kt[(c4 * 4 + 2) * AT_STRIDE + r] = kv.z;
            Kt[(c4 * 4 + 3) * AT_STRIDE + r] = kv.w;
            float4 vv = *(const float4*)(Vb + (size_t)(j0 + r) * Dm + c4 * 4);
            *(float4*)&Vs[r * AT_STRIDE + c4 * 4] = vv;
        }
        __syncthreads();

        // S = Q @ K^T * scale   (thread owns rows ty*4+a, cols tx*4+c)
        float s[4][4];
        #pragma unroll
        for (int a = 0; a < 4; a++)
            #pragma unroll
            for (int c = 0; c < 4; c++) s[a][c] = 0.f;

        #pragma unroll 4
        for (int d = 0; d < DHd; d++) {
            float4 tq = *(float4*)&Qt[d * AT_STRIDE + ty * 4];
            float4 tk = *(float4*)&Kt[d * AT_STRIDE + tx * 4];
            float qa[4] = {tq.x, tq.y, tq.z, tq.w};
            float kc[4] = {tk.x, tk.y, tk.z, tk.w};
            #pragma unroll
            for (int a = 0; a < 4; a++)
                #pragma unroll
                for (int c = 0; c < 4; c++)
                    s[a][c] += qa[a] * kc[c];
        }

        // Online softmax update per row
        #pragma unroll
        for (int a = 0; a < 4; a++) {
            float s0 = s[a][0] * scale, s1 = s[a][1] * scale;
            float s2 = s[a][2] * scale, s3 = s[a][3] * scale;
            float rm = fmaxf(fmaxf(s0, s1), fmaxf(s2, s3));
            #pragma unroll
            for (int off = 8; off; off >>= 1)
                rm = fmaxf(rm, __shfl_xor_sync(0xffffffffu, rm, off, 16));
            float mn = fmaxf(m[a], rm);
            float corr = __expf(m[a] - mn);
            float p0 = __expf(s0 - mn), p1 = __expf(s1 - mn);
            float p2 = __expf(s2 - mn), p3 = __expf(s3 - mn);
            float rs = p0 + p1 + p2 + p3;
            #pragma unroll
            for (int off = 8; off; off >>= 1)
                rs += __shfl_xor_sync(0xffffffffu, rs, off, 16);
            l[a] = l[a] * corr + rs;
            m[a] = mn;
            #pragma unroll
            for (int d = 0; d < 4; d++) o[a][d] *= corr;
            int r = ty * 4 + a;
            Ps[r * AT_STRIDE + tx * 4 + 0] = p0;
            Ps[r * AT_STRIDE + tx * 4 + 1] = p1;
            Ps[r * AT_STRIDE + tx * 4 + 2] = p2;
            Ps[r * AT_STRIDE + tx * 4 + 3] = p3;
        }
        __syncthreads();

        // O += P @ V   (thread owns rows ty*4+a, out-dims tx*4+d)
        #pragma unroll 4
        for (int c0 = 0; c0 < 64; c0 += 4) {
            float pa[4][4];
            #pragma unroll
            for (int a = 0; a < 4; a++) {
                float4 p4 = *(float4*)&Ps[(ty * 4 + a) * AT_STRIDE + c0];
                pa[a][0] = p4.x; pa[a][1] = p4.y; pa[a][2] = p4.z; pa[a][3] = p4.w;
            }
            #pragma unroll
            for (int cc = 0; cc < 4; cc++) {
                float4 vv = *(float4*)&Vs[(c0 + cc) * AT_STRIDE + tx * 4];
                #pragma unroll
                for (int a = 0; a < 4; a++) {
                    o[a][0] += pa[a][cc] * vv.x;
                    o[a][1] += pa[a][cc] * vv.y;
                    o[a][2] += pa[a][cc] * vv.z;
                    o[a][3] += pa[a][cc] * vv.w;
                }
            }
        }
    }

    // Normalize and write out (already in [B,S,H*DH] layout)
    #pragma unroll
    for (int a = 0; a < 4; a++) {
        float inv = 1.f / l[a];
        float4 ov;
        ov.x = o[a][0] * inv; ov.y = o[a][1] * inv;
        ov.z = o[a][2] * inv; ov.w = o[a][3] * inv;
        *(float4*)(Ob + (size_t)(q0 + ty * 4 + a) * Dm + tx * 4) = ov;
    }
}

// ---------------- LayerNorm + residual: out = res + LN(x)*g + b ---------------
__global__ __launch_bounds__(256) void ln_residual_kernel(
    const float* __restrict__ res, const float* __restrict__ x,
    const float* __restrict__ g, const float* __restrict__ be,
    float* __restrict__ out)
{
    const int row = blockIdx.x;
    const int tid = threadIdx.x;
    const float* xr = x + (size_t)row * Dm;

    float4 v = *(const float4*)(xr + tid * 4);
    float s1 = v.x + v.y + v.z + v.w;
    float s2 = v.x * v.x + v.y * v.y + v.z * v.z + v.w * v.w;
    #pragma unroll
    for (int off = 16; off; off >>= 1) {
        s1 += __shfl_xor_sync(0xffffffffu, s1, off);
        s2 += __shfl_xor_sync(0xffffffffu, s2, off);
    }
    __shared__ float r1[8], r2[8];
    if ((tid & 31) == 0) { r1[tid >> 5] = s1; r2[tid >> 5] = s2; }
    __syncthreads();
    float t1 = 0.f, t2 = 0.f;
    #pragma unroll
    for (int w = 0; w < 8; w++) { t1 += r1[w]; t2 += r2[w]; }

    const float mu  = t1 * (1.f / Dm);
    const float var = t2 * (1.f / Dm) - mu * mu;
    const float rstd = rsqrtf(var + 1e-6f);

    float4 rv = *(const float4*)(res + (size_t)row * Dm + tid * 4);
    float4 gv = *(const float4*)(g + tid * 4);
    float4 bv = *(const float4*)(be + tid * 4);
    float4 ov;
    ov.x = rv.x + (v.x - mu) * rstd * gv.x + bv.x;
    ov.y = rv.y + (v.y - mu) * rstd * gv.y + bv.y;
    ov.z = rv.z + (v.z - mu) * rstd * gv.z + bv.z;
    ov.w = rv.w + (v.w - mu) * rstd * gv.w + bv.w;
    *(float4*)(out + (size_t)row * Dm + tid * 4) = ov;
}

// ---------------- launch ------------------------------------------------------
extern "C" void kernel_launch(void* const* d_in, const int* in_sizes, int n_in,
                              void* d_out, int out_size)
{
    const float* x_enc = (const float*)d_in[0];
    const float* x_pos = (const float*)d_in[1];
    const float* wq = (const float*)d_in[2];  const float* bq = (const float*)d_in[3];
    const float* wk = (const float*)d_in[4];  const float* bk = (const float*)d_in[5];
    const float* wv = (const float*)d_in[6];  const float* bv = (const float*)d_in[7];
    const float* wc = (const float*)d_in[8];  const float* bc = (const float*)d_in[9];
    const float* w1 = (const float*)d_in[10]; const float* b1 = (const float*)d_in[11];
    const float* w2 = (const float*)d_in[12]; const float* b2 = (const float*)d_in[13];
    const float* g1 = (const float*)d_in[14]; const float* be1 = (const float*)d_in[15];
    const float* g2 = (const float*)d_in[16]; const float* be2 = (const float*)d_in[17];
    float* out = (float*)d_out;

    float *gx, *gq, *gk, *gv, *gattn, *gproj, *ga, *gh1, *gffn;
    cudaGetSymbolAddress((void**)&gx,    g_x);
    cudaGetSymbolAddress((void**)&gq,    g_q);
    cudaGetSymbolAddress((void**)&gk,    g_k);
    cudaGetSymbolAddress((void**)&gv,    g_v);
    cudaGetSymbolAddress((void**)&gattn, g_attn);
    cudaGetSymbolAddress((void**)&gproj, g_proj);
    cudaGetSymbolAddress((void**)&ga,    g_a);
    cudaGetSymbolAddress((void**)&gh1,   g_h1);
    cudaGetSymbolAddress((void**)&gffn,  g_ffn);

    cudaFuncSetAttribute(flash_attn_kernel,
                         cudaFuncAttributeMaxDynamicSharedMemorySize, AT_SMEM);

    // x = x_enc + x_pos
    const int n4 = NTOK * Dm / 4;
    add_kernel<<<n4 / 256, 256>>>(x_enc, x_pos, gx, n4);

    // QKV projections
    dim3 gridP(Dm / GBN, NTOK / GBM);
    gemm_bias_kernel<<<gridP, 256>>>(gx, wq, bq, gq, NTOK, Dm, Dm, 0);
    gemm_bias_kernel<<<gridP, 256>>>(gx, wk, bk, gk, NTOK, Dm, Dm, 0);
    gemm_bias_kernel<<<gridP, 256>>>(gx, wv, bv, gv, NTOK, Dm, Dm, 0);

    // Attention (fused softmax, writes [B,S,D] directly)
    flash_attn_kernel<<<dim3(Sq / 64, Bsz * Hh), 256, AT_SMEM>>>(gq, gk, gv, gattn);

    // Output projection
    gemm_bias_kernel<<<gridP, 256>>>(gattn, wc, bc, gproj, NTOK, Dm, Dm, 0);

    // a = x + LN(proj)
    ln_residual_kernel<<<NTOK, 256>>>(gx, gproj, g1, be1, ga);

    // FFN
    dim3 gridF1(Ff / GBN, NTOK / GBM);
    gemm_bias_kernel<<<gridF1, 256>>>(ga, w1, b1, gh1, NTOK, Ff, Dm, 1);
    dim3 gridF2(Dm / GBN, NTOK / GBM);
    gemm_bias_kernel<<<gridF2, 256>>>(gh1, w2, b2, gffn, NTOK, Dm, Ff, 0);

    // out = a + LN(ffn)
    ln_residual_kernel<<<NTOK, 256>>>(ga, gffn, g2, be2, out);
}

// round 3
// speedup vs baseline: 2.1071x; 2.1071x over previous
#include <cuda_runtime.h>
#include <cuda_bf16.h>
#include <cstdint>
#include <math.h>

#define Bsz 2
#define Sq 2048
#define Dm 1024
#define Hh 16
#define DHd 64
#define Ff 4096
#define NTOK (Bsz*Sq)

typedef __nv_bfloat16 bf16;

// tcgen05 only exists in the arch-specific (sm_103a / sm_100a) device pass.
#if defined(__CUDA_ARCH__) && (defined(__CUDA_ARCH_FEAT_SM103_ALL) || defined(__CUDA_ARCH_FEAT_SM100_ALL) || (defined(__CUDA_ARCH_SPECIFIC__) && (__CUDA_ARCH_SPECIFIC__ >= 1000)))
#define USE_TCGEN05 1
#else
#define USE_TCGEN05 0
#endif

// ---------------- scratch (device globals) ------------------------------------
__device__ float g_x[(size_t)NTOK*Dm];
__device__ bf16  g_xh[(size_t)NTOK*Dm];
__device__ bf16  g_xl[(size_t)NTOK*Dm];

__device__ bf16 g_wqh[(size_t)Dm*Dm], g_wql[(size_t)Dm*Dm];
__device__ bf16 g_wkh[(size_t)Dm*Dm], g_wkl[(size_t)Dm*Dm];
__device__ bf16 g_wvh[(size_t)Dm*Dm], g_wvl[(size_t)Dm*Dm];
__device__ bf16 g_wch[(size_t)Dm*Dm], g_wcl[(size_t)Dm*Dm];
__device__ bf16 g_w1h[(size_t)Ff*Dm], g_w1l[(size_t)Ff*Dm];   // transposed [N=F, K=D]
__device__ bf16 g_w2h[(size_t)Dm*Ff], g_w2l[(size_t)Dm*Ff];   // transposed [N=D, K=F]

__device__ float g_q[(size_t)NTOK*Dm];
__device__ float g_k[(size_t)NTOK*Dm];
__device__ float g_v[(size_t)NTOK*Dm];
__device__ bf16  g_ath[(size_t)NTOK*Dm], g_atl[(size_t)NTOK*Dm];
__device__ float g_proj[(size_t)NTOK*Dm];
__device__ float g_a[(size_t)NTOK*Dm];
__device__ bf16  g_ah[(size_t)NTOK*Dm], g_al[(size_t)NTOK*Dm];
__device__ bf16  g_h1h[(size_t)NTOK*Ff], g_h1l[(size_t)NTOK*Ff];
__device__ float g_ffn[(size_t)NTOK*Dm];

// ---------------- common helpers ----------------------------------------------
__device__ __forceinline__ uint32_t smem_u32(const void* p){
    uint32_t a;
    asm("{ .reg .u64 t; cvta.to.shared.u64 t, %1; cvt.u32.u64 %0, t; }" : "=r"(a) : "l"(p));
    return a;
}
#define SWZ(x) ((x) ^ (((x) >> 3) & 0x70))

__device__ __forceinline__ void split2(float v, bf16& h, bf16& l){
    h = __float2bfloat16(v);
    l = __float2bfloat16(v - __bfloat162float(h));
}

#if USE_TCGEN05
__device__ __forceinline__ uint32_t elect_one(){
    uint32_t p;
    asm volatile("{\n\t.reg .pred p;\n\telect.sync _|p, 0xFFFFFFFF;\n\tselp.b32 %0, 1, 0, p;\n\t}" : "=r"(p));
    return p;
}
__device__ __forceinline__ uint64_t make_desc(uint32_t addr){
    // SW128, version=1 (Blackwell), SBO=64, LBO=1, K-major
    return ((uint64_t)2 << 61) | ((uint64_t)1 << 46) | ((uint64_t)64 << 32)
         | ((uint64_t)1 << 16) | ((uint64_t)(addr >> 4) & 0x3FFF);
}
__device__ __forceinline__ void mma_f16_ss(uint32_t d, uint64_t a, uint64_t b,
                                           uint32_t idesc, uint32_t en){
    asm volatile(
        "{\n\t.reg .pred p;\n\tsetp.ne.u32 p, %4, 0;\n\t"
        "tcgen05.mma.cta_group::1.kind::f16 [%0], %1, %2, %3, {%5,%5,%5,%5}, p;\n\t}"
        :: "r"(d), "l"(a), "l"(b), "r"(idesc), "r"(en), "r"(0u) : "memory");
}
__device__ __forceinline__ void mbar_wait(uint32_t mbar, int parity){
    asm volatile(
        "{\n\t.reg .pred P;\n\t"
        "WL_%=:\n\t"
        "mbarrier.try_wait.parity.acquire.cta.shared::cta.b64 P, [%0], %1, 0x989680;\n\t"
        "@P bra.uni WD_%=;\n\t"
        "bra.uni WL_%=;\n\t"
        "WD_%=:\n\t}"
        :: "r"(mbar), "r"(parity) : "memory");
}
#define LDTM_X32(r, addr) \
    asm volatile( \
        "tcgen05.ld.sync.aligned.32x32b.x32.b32 " \
        "{%0, %1, %2, %3, %4, %5, %6, %7, " \
        " %8, %9, %10, %11, %12, %13, %14, %15, " \
        " %16, %17, %18, %19, %20, %21, %22, %23, " \
        " %24, %25, %26, %27, %28, %29, %30, %31}, [%32];" \
        : "=r"((r)[0]),  "=r"((r)[1]),  "=r"((r)[2]),  "=r"((r)[3]), \
          "=r"((r)[4]),  "=r"((r)[5]),  "=r"((r)[6]),  "=r"((r)[7]), \
          "=r"((r)[8]),  "=r"((r)[9]),  "=r"((r)[10]), "=r"((r)[11]), \
          "=r"((r)[12]), "=r"((r)[13]), "=r"((r)[14]), "=r"((r)[15]), \
          "=r"((r)[16]), "=r"((r)[17]), "=r"((r)[18]), "=r"((r)[19]), \
          "=r"((r)[20]), "=r"((r)[21]), "=r"((r)[22]), "=r"((r)[23]), \
          "=r"((r)[24]), "=r"((r)[25]), "=r"((r)[26]), "=r"((r)[27]), \
          "=r"((r)[28]), "=r"((r)[29]), "=r"((r)[30]), "=r"((r)[31]) \
        : "r"(addr))
#else
// legacy tensor-core path (legal on family-generic sm_103)
__device__ __forceinline__ void ldsm_x4(uint32_t& r0, uint32_t& r1, uint32_t& r2,
                                        uint32_t& r3, uint32_t addr){
    asm volatile("ldmatrix.sync.aligned.m8n8.x4.shared.b16 {%0,%1,%2,%3}, [%4];"
                 : "=r"(r0), "=r"(r1), "=r"(r2), "=r"(r3) : "r"(addr));
}
__device__ __forceinline__ void mma16816(float* c, const uint32_t* a, const uint32_t* b){
    asm volatile(
        "mma.sync.aligned.m16n8k16.row.col.f32.bf16.bf16.f32 "
        "{%0,%1,%2,%3}, {%4,%5,%6,%7}, {%8,%9}, {%0,%1,%2,%3};"
        : "+f"(c[0]), "+f"(c[1]), "+f"(c[2]), "+f"(c[3])
        : "r"(a[0]), "r"(a[1]), "r"(a[2]), "r"(a[3]), "r"(b[0]), "r"(b[1]));
}
#endif

// ---------------- x = a + b, emit fp32 + bf16 hi/lo ---------------------------
__global__ __launch_bounds__(256) void add_convert(
    const float* __restrict__ a, const float* __restrict__ b,
    float* __restrict__ o, bf16* __restrict__ oh, bf16* __restrict__ ol, int n4)
{
    int i = blockIdx.x * 256 + threadIdx.x;
    if (i >= n4) return;
    float4 av = ((const float4*)a)[i];
    float4 bv = ((const float4*)b)[i];
    float4 v;
    v.x = av.x + bv.x; v.y = av.y + bv.y; v.z = av.z + bv.z; v.w = av.w + bv.w;
    ((float4*)o)[i] = v;
    bf16 h[4], l[4];
    split2(v.x, h[0], l[0]); split2(v.y, h[1], l[1]);
    split2(v.z, h[2], l[2]); split2(v.w, h[3], l[3]);
    *(uint2*)(oh + (size_t)i * 4) = *(uint2*)h;
    *(uint2*)(ol + (size_t)i * 4) = *(uint2*)l;
}

// ---------------- weight transpose + split: W[K,N] -> Wt_hi/lo[N,K] -----------
__global__ __launch_bounds__(256) void wconvert_t(
    const float* __restrict__ W, bf16* __restrict__ Th, bf16* __restrict__ Tl,
    int K, int N)
{
    __shared__ float t[32][33];
    int n0 = blockIdx.x * 32, k0 = blockIdx.y * 32;
    int x = threadIdx.x, y = threadIdx.y;   // (32,8)
    #pragma unroll
    for (int i = 0; i < 4; i++)
        t[y + 8*i][x] = W[(size_t)(k0 + y + 8*i) * N + n0 + x];
    __syncthreads();
    #pragma unroll
    for (int i = 0; i < 4; i++) {
        float v = t[x][y + 8*i];
        bf16 h, l; split2(v, h, l);
        size_t idx = (size_t)(n0 + y + 8*i) * K + k0 + x;
        Th[idx] = h; Tl[idx] = l;
    }
}

// ---------------- bf16x3 GEMM: C = (Ah+Al)[M,K] @ (Bh+Bl)[N,K]^T + bias -------
// 128x128 CTA tile, BK=64, 256 threads. Two SW128-swizzled 64KB smem stages:
// per stage Ah@0, Al@16K, Bh@32K, Bl@48K, each 128 rows x 128 bytes.
#define TBM 128
#define TBN 128
#define TBK 64
#define STG 65536
#define SM_BASE 1024
#define GEMM_SMEM (SM_BASE + 2*STG)

__global__ __launch_bounds__(256, 1) void gemm_tc(
    const uint4* __restrict__ Ah4, const uint4* __restrict__ Al4,
    const uint4* __restrict__ Bh4, const uint4* __restrict__ Bl4,
    const float* __restrict__ bias,
    float* __restrict__ Cf, bf16* __restrict__ Ch, bf16* __restrict__ Cl,
    int M, int N, int K, int relu)
{
    extern __shared__ char smbuf[];
    const int tid = threadIdx.x;
    const int wid = tid >> 5;
    const int lane = tid & 31;
    const uint32_t sbase = smem_u32(smbuf);

    const int rowBase = blockIdx.y * TBM;
    const int colBase = blockIdx.x * TBN;
    const int K8 = K >> 3;
    const int nch = K / TBK;

    uint4 pf[16];
    auto ldg_stage = [&](int i){
        const int kc8 = i * 8;
        #pragma unroll
        for (int t = 0; t < 4; t++) {
            int id = tid + t * 256;
            int r = id >> 3, c = id & 7;
            size_t goA = (size_t)(rowBase + r) * K8 + kc8 + c;
            size_t goB = (size_t)(colBase + r) * K8 + kc8 + c;
            pf[t]      = Ah4[goA];
            pf[4 + t]  = Al4[goA];
            pf[8 + t]  = Bh4[goB];
            pf[12 + t] = Bl4[goB];
        }
    };
    auto sts_stage = [&](int buf){
        char* st = smbuf + SM_BASE + buf * STG;
        #pragma unroll
        for (int t = 0; t < 4; t++) {
            int id = tid + t * 256;
            int r = id >> 3, c = id & 7;
            uint32_t sw = SWZ(r * 128 + c * 16);
            *(uint4*)(st + sw)          = pf[t];
            *(uint4*)(st + 16384 + sw)  = pf[4 + t];
            *(uint4*)(st + 32768 + sw)  = pf[8 + t];
            *(uint4*)(st + 49152 + sw)  = pf[12 + t];
        }
    };

#if USE_TCGEN05
    // ---- tcgen05 path ----
    if (wid == 0)
        asm volatile("tcgen05.alloc.cta_group::1.sync.aligned.shared::cta.b32 [%0], %1;"
                     :: "r"(sbase), "r"(128) : "memory");
    if (tid == 0) {
        asm volatile("mbarrier.init.shared.b64 [%0], 1;" :: "r"(sbase + 16) : "memory");
        asm volatile("mbarrier.init.shared.b64 [%0], 1;" :: "r"(sbase + 24) : "memory");
    }
    __syncthreads();
    uint32_t tmem;
    asm volatile("ld.shared.b32 %0, [%1];" : "=r"(tmem) : "r"(sbase));

    uint64_t dAh[2], dAl[2], dBh[2], dBl[2];
    #pragma unroll
    for (int s = 0; s < 2; s++) {
        uint32_t b = sbase + SM_BASE + s * STG;
        dAh[s] = make_desc(b);
        dAl[s] = make_desc(b + 16384);
        dBh[s] = make_desc(b + 32768);
        dBl[s] = make_desc(b + 49152);
    }
    const uint32_t IDESC = (1u<<4) | (1u<<7) | (1u<<10) | (16u<<17) | (8u<<24);

    ldg_stage(0);
    sts_stage(0);
    asm volatile("fence.proxy.async.shared::cta;" ::: "memory");
    __syncthreads();

    int ph[2] = {0, 0};
    for (int i = 0; i < nch; i++) {
        const int s = i & 1;
        if (wid == 0 && elect_one()) {
            #pragma unroll
            for (int k = 0; k < 4; k++) {
                uint64_t oa = (uint64_t)(k * 2);
                uint32_t en0 = (i == 0 && k == 0) ? 0u : 1u;
                mma_f16_ss(tmem, dAh[s] + oa, dBh[s] + oa, IDESC, en0);
                mma_f16_ss(tmem, dAh[s] + oa, dBl[s] + oa, IDESC, 1u);
                mma_f16_ss(tmem, dAl[s] + oa, dBh[s] + oa, IDESC, 1u);
            }
            asm volatile(
                "tcgen05.commit.cta_group::1.mbarrier::arrive::one.shared::cluster.b64 [%0];"
                :: "r"(sbase + 16 + s * 8) : "memory");
        }
        if (i + 1 < nch) {
            ldg_stage(i + 1);
            const int s2 = (i + 1) & 1;
            if (i >= 1) { mbar_wait(sbase + 16 + s2 * 8, ph[s2]); ph[s2] ^= 1; }
            sts_stage(s2);
            asm volatile("fence.proxy.async.shared::cta;" ::: "memory");
        }
        __syncthreads();
    }
    // last two commits outstanding
    { const int s2 = (nch - 2) & 1; mbar_wait(sbase + 16 + s2 * 8, ph[s2]); ph[s2] ^= 1; }
    { const int s2 = (nch - 1) & 1; mbar_wait(sbase + 16 + s2 * 8, ph[s2]); ph[s2] ^= 1; }
    asm volatile("tcgen05.fence::after_thread_sync;" ::: "memory");

    if (wid < 4) {
        const int row = rowBase + wid * 32 + lane;
        #pragma unroll
        for (int cc = 0; cc < 128; cc += 32) {
            uint32_t dr[32];
            LDTM_X32(dr, tmem + cc);
            asm volatile("tcgen05.wait::ld.sync.aligned;" ::: "memory");
            int col = colBase + cc;
            float v[32];
            #pragma unroll
            for (int j = 0; j < 32; j++) {
                v[j] = __uint_as_float(dr[j]) + bias[col + j];
                if (relu) v[j] = fmaxf(v[j], 0.f);
            }
            if (Cf) {
                #pragma unroll
                for (int j = 0; j < 32; j += 4) {
                    float4 o4 = {v[j], v[j+1], v[j+2], v[j+3]};
                    *(float4*)(Cf + (size_t)row * N + col + j) = o4;
                }
            }
            if (Ch) {
                bf16 hv[32], lv[32];
                #pragma unroll
                for (int j = 0; j < 32; j++) split2(v[j], hv[j], lv[j]);
                #pragma unroll
                for (int j = 0; j < 32; j += 8) {
                    *(uint4*)(Ch + (size_t)row * N + col + j) = *(uint4*)(hv + j);
                    *(uint4*)(Cl + (size_t)row * N + col + j) = *(uint4*)(lv + j);
                }
            }
        }
    }
    __syncthreads();
    if (wid == 0)
        asm volatile("tcgen05.dealloc.cta_group::1.sync.aligned.b32 %0, %1;"
                     :: "r"(tmem), "r"(128));
#else
    // ---- mma.sync bf16 fallback (tensor cores on family-generic target) ----
    const int wm = (wid & 1) * 64;       // warp M offset
    const int wn = (wid >> 1) * 32;      // warp N offset

    float acc[4][4][4];
    #pragma unroll
    for (int mt = 0; mt < 4; mt++)
        #pragma unroll
        for (int nt = 0; nt < 4; nt++)
            #pragma unroll
            for (int e = 0; e < 4; e++) acc[mt][nt][e] = 0.f;

    auto compute = [&](int buf){
        const uint32_t ab = sbase + SM_BASE + buf * STG;
        #pragma unroll
        for (int ks = 0; ks < 4; ks++) {
            const int kb = ks * 32;   // byte offset of k16 chunk
            uint32_t ah[4][4], al[4][4], bh[2][4], bl[2][4];
            #pragma unroll
            for (int mt = 0; mt < 4; mt++) {
                uint32_t off = SWZ((wm + mt*16 + (lane & 15)) * 128 + kb + (lane >> 4) * 16);
                ldsm_x4(ah[mt][0], ah[mt][1], ah[mt][2], ah[mt][3], ab + off);
                ldsm_x4(al[mt][0], al[mt][1], al[mt][2], al[mt][3], ab + 16384 + off);
            }
            #pragma unroll
            for (int p = 0; p < 2; p++) {
                uint32_t off = SWZ((wn + p*16 + (lane & 15)) * 128 + kb + (lane >> 4) * 16);
                ldsm_x4(bh[p][0], bh[p][1], bh[p][2], bh[p][3], ab + 32768 + off);
                ldsm_x4(bl[p][0], bl[p][1], bl[p][2], bl[p][3], ab + 49152 + off);
            }
            #pragma unroll
            for (int mt = 0; mt < 4; mt++) {
                #pragma unroll
                for (int nt = 0; nt < 4; nt++) {
                    uint32_t fh[2] = { bh[nt >> 1][nt & 1], bh[nt >> 1][2 + (nt & 1)] };
                    uint32_t fl[2] = { bl[nt >> 1][nt & 1], bl[nt >> 1][2 + (nt & 1)] };
                    mma16816(acc[mt][nt], ah[mt], fh);
                    mma16816(acc[mt][nt], ah[mt], fl);
                    mma16816(acc[mt][nt], al[mt], fh);
                }
            }
        }
    };

    ldg_stage(0);
    sts_stage(0);
    __syncthreads();
    for (int i = 0; i < nch; i++) {
        const bool more = (i + 1 < nch);
        if (more) ldg_stage(i + 1);
        compute(i & 1);
        if (more) sts_stage((i + 1) & 1);
        __syncthreads();
    }

    // epilogue from registers
    #pragma unroll
    for (int mt = 0; mt < 4; mt++) {
        #pragma unroll
        for (int nt = 0; nt < 4; nt++) {
            int r0 = rowBase + wm + mt*16 + (lane >> 2);
            int c0 = colBase + wn + nt*8 + (lane & 3) * 2;
            float2 bb = *(const float2*)(bias + c0);
            #pragma unroll
            for (int half = 0; half < 2; half++) {
                int r = r0 + half * 8;
                float vx = acc[mt][nt][half*2 + 0] + bb.x;
                float vy = acc[mt][nt][half*2 + 1] + bb.y;
                if (relu) { vx = fmaxf(vx, 0.f); vy = fmaxf(vy, 0.f); }
                if (Cf) {
                    float2 o2 = {vx, vy};
                    *(float2*)(Cf + (size_t)r * N + c0) = o2;
                }
                if (Ch) {
                    bf16 hx, lx, hy, ly;
                    split2(vx, hx, lx); split2(vy, hy, ly);
                    bf16 hp[2] = {hx, hy}, lp[2] = {lx, ly};
                    *(uint32_t*)(Ch + (size_t)r * N + c0) = *(uint32_t*)hp;
                    *(uint32_t*)(Cl + (size_t)r * N + c0) = *(uint32_t*)lp;
                }
            }
        }
    }
#endif
}

// ---------------- Flash attention (fp32, online softmax), bf16 hi/lo out ------
#define AT_STRIDE 68
#define AT_SMEM (4 * 64 * AT_STRIDE * 4)

__global__ __launch_bounds__(256) void flash_attn_kernel(
    const float* __restrict__ Q, const float* __restrict__ K,
    const float* __restrict__ V, bf16* __restrict__ Oh, bf16* __restrict__ Ol)
{
    extern __shared__ float smf[];
    float* Qt = smf;
    float* Kt = smf + 64 * AT_STRIDE;
    float* Vs = smf + 2 * 64 * AT_STRIDE;
    float* Ps = smf + 3 * 64 * AT_STRIDE;

    const int tid = threadIdx.x;
    const int tx = tid & 15;
    const int ty = tid >> 4;
    const int bh = blockIdx.y;
    const int b = bh >> 4, h = bh & 15;
    const int q0 = blockIdx.x * 64;

    const float* Qb = Q + (size_t)b * Sq * Dm + h * DHd;
    const float* Kb = K + (size_t)b * Sq * Dm + h * DHd;
    const float* Vb = V + (size_t)b * Sq * Dm + h * DHd;
    bf16* Ohb = Oh + (size_t)b * Sq * Dm + h * DHd;
    bf16* Olb = Ol + (size_t)b * Sq * Dm + h * DHd;

    #pragma unroll
    for (int t = 0; t < 4; t++) {
        int id = tid + t * 256;
        int r = id >> 4, c4 = id & 15;
        float4 v = *(const float4*)(Qb + (size_t)(q0 + r) * Dm + c4 * 4);
        Qt[(c4 * 4 + 0) * AT_STRIDE + r] = v.x;
        Qt[(c4 * 4 + 1) * AT_STRIDE + r] = v.y;
        Qt[(c4 * 4 + 2) * AT_STRIDE + r] = v.z;
        Qt[(c4 * 4 + 3) * AT_STRIDE + r] = v.w;
    }

    float o[4][4];
    float m[4], l[4];
    #pragma unroll
    for (int a = 0; a < 4; a++) {
        m[a] = -1e30f; l[a] = 0.f;
        #pragma unroll
        for (int d = 0; d < 4; d++) o[a][d] = 0.f;
    }
    const float scale = 0.125f;

    for (int j0 = 0; j0 < Sq; j0 += 64) {
        __syncthreads();
        #pragma unroll
        for (int t = 0; t < 4; t++) {
            int id = tid + t * 256;
            int r = id >> 4, c4 = id & 15;
            float4 kv = *(const float4*)(Kb + (size_t)(j0 + r) * Dm + c4 * 4);
            Kt[(c4 * 4 + 0) * AT_STRIDE + r] = kv.x;
            Kt[(c4 * 4 + 1) * AT_STRIDE + r] = kv.y;
            Kt[(c4 * 4 + 2) * AT_STRIDE + r] = kv.z;
            Kt[(c4 * 4 + 3) * AT_STRIDE + r] = kv.w;
            float4 vv = *(const float4*)(Vb + (size_t)(j0 + r) * Dm + c4 * 4);
            *(float4*)&Vs[r * AT_STRIDE + c4 * 4] = vv;
        }
        __syncthreads();

        float s[4][4];
        #pragma unroll
        for (int a = 0; a < 4; a++)
            #pragma unroll
            for (int c = 0; c < 4; c++) s[a][c] = 0.f;

        #pragma unroll 4
        for (int d = 0; d < DHd; d++) {
            float4 tq = *(float4*)&Qt[d * AT_STRIDE + ty * 4];
            float4 tk = *(float4*)&Kt[d * AT_STRIDE + tx * 4];
            float qa[4] = {tq.x, tq.y, tq.z, tq.w};
            float kc[4] = {tk.x, tk.y, tk.z, tk.w};
            #pragma unroll
            for (int a = 0; a < 4; a++)
                #pragma unroll
                for (int c = 0; c < 4; c++)
                    s[a][c] += qa[a] * kc[c];
        }

        #pragma unroll
        for (int a = 0; a < 4; a++) {
            float s0 = s[a][0] * scale, s1 = s[a][1] * scale;
            float s2 = s[a][2] * scale, s3 = s[a][3] * scale;
            float rm = fmaxf(fmaxf(s0, s1), fmaxf(s2, s3));
            #pragma unroll
            for (int off = 8; off; off >>= 1)
                rm = fmaxf(rm, __shfl_xor_sync(0xffffffffu, rm, off, 16));
            float mn = fmaxf(m[a], rm);
            float corr = __expf(m[a] - mn);
            float p0 = __expf(s0 - mn), p1 = __expf(s1 - mn);
            float p2 = __expf(s2 - mn), p3 = __expf(s3 - mn);
            float rs = p0 + p1 + p2 + p3;
            #pragma unroll
            for (int off = 8; off; off >>= 1)
                rs += __shfl_xor_sync(0xffffffffu, rs, off, 16);
            l[a] = l[a] * corr + rs;
            m[a] = mn;
            #pragma unroll
            for (int d = 0; d < 4; d++) o[a][d] *= corr;
            int r = ty * 4 + a;
            Ps[r * AT_STRIDE + tx * 4 + 0] = p0;
            Ps[r * AT_STRIDE + tx * 4 + 1] = p1;
            Ps[r * AT_STRIDE + tx * 4 + 2] = p2;
            Ps[r * AT_STRIDE + tx * 4 + 3] = p3;
        }
        __syncthreads();

        #pragma unroll 4
        for (int c0 = 0; c0 < 64; c0 += 4) {
            float pa[4][4];
            #pragma unroll
            for (int a = 0; a < 4; a++) {
                float4 p4 = *(float4*)&Ps[(ty * 4 + a) * AT_STRIDE + c0];
                pa[a][0] = p4.x; pa[a][1] = p4.y; pa[a][2] = p4.z; pa[a][3] = p4.w;
            }
            #pragma unroll
            for (int cc = 0; cc < 4; cc++) {
                float4 vv = *(float4*)&Vs[(c0 + cc) * AT_STRIDE + tx * 4];
                #pragma unroll
                for (int a = 0; a < 4; a++) {
                    o[a][0] += pa[a][cc] * vv.x;
                    o[a][1] += pa[a][cc] * vv.y;
                    o[a][2] += pa[a][cc] * vv.z;
                    o[a][3] += pa[a][cc] * vv.w;
                }
            }
        }
    }

    #pragma unroll
    for (int a = 0; a < 4; a++) {
        float inv = 1.f / l[a];
        bf16 hb[4], lb[4];
        split2(o[a][0] * inv, hb[0], lb[0]);
        split2(o[a][1] * inv, hb[1], lb[1]);
        split2(o[a][2] * inv, hb[2], lb[2]);
        split2(o[a][3] * inv, hb[3], lb[3]);
        size_t idx = (size_t)(q0 + ty * 4 + a) * Dm + tx * 4;
        *(uint2*)(Ohb + idx) = *(uint2*)hb;
        *(uint2*)(Olb + idx) = *(uint2*)lb;
    }
}

// ---------------- LayerNorm + residual, optional bf16 hi/lo out ---------------
__global__ __launch_bounds__(256) void ln_residual_kernel(
    const float* __restrict__ res, const float* __restrict__ x,
    const float* __restrict__ g, const float* __restrict__ be,
    float* __restrict__ out, bf16* __restrict__ oh, bf16* __restrict__ ol)
{
    const int row = blockIdx.x;
    const int tid = threadIdx.x;
    const float* xr = x + (size_t)row * Dm;

    float4 v = *(const float4*)(xr + tid * 4);
    float s1 = v.x + v.y + v.z + v.w;
    float s2 = v.x * v.x + v.y * v.y + v.z * v.z + v.w * v.w;
    #pragma unroll
    for (int off = 16; off; off >>= 1) {
        s1 += __shfl_xor_sync(0xffffffffu, s1, off);
        s2 += __shfl_xor_sync(0xffffffffu, s2, off);
    }
    __shared__ float r1[8], r2[8];
    if ((tid & 31) == 0) { r1[tid >> 5] = s1; r2[tid >> 5] = s2; }
    __syncthreads();
    float t1 = 0.f, t2 = 0.f;
    #pragma unroll
    for (int w = 0; w < 8; w++) { t1 += r1[w]; t2 += r2[w]; }

    const float mu  = t1 * (1.f / Dm);
    const float var = t2 * (1.f / Dm) - mu * mu;
    const float rstd = rsqrtf(var + 1e-6f);

    float4 rv = *(const float4*)(res + (size_t)row * Dm + tid * 4);
    float4 gv = *(const float4*)(g + tid * 4);
    float4 bv = *(const float4*)(be + tid * 4);
    float4 ov;
    ov.x = rv.x + (v.x - mu) * rstd * gv.x + bv.x;
    ov.y = rv.y + (v.y - mu) * rstd * gv.y + bv.y;
    ov.z = rv.z + (v.z - mu) * rstd * gv.z + bv.z;
    ov.w = rv.w + (v.w - mu) * rstd * gv.w + bv.w;
    *(float4*)(out + (size_t)row * Dm + tid * 4) = ov;
    if (oh) {
        bf16 h[4], l[4];
        split2(ov.x, h[0], l[0]); split2(ov.y, h[1], l[1]);
        split2(ov.z, h[2], l[2]); split2(ov.w, h[3], l[3]);
        size_t idx = (size_t)row * Dm + tid * 4;
        *(uint2*)(oh + idx) = *(uint2*)h;
        *(uint2*)(ol + idx) = *(uint2*)l;
    }
}

// ---------------- launch --------------------------------------------------------
extern "C" void kernel_launch(void* const* d_in, const int* in_sizes, int n_in,
                              void* d_out, int out_size)
{
    const float* x_enc = (const float*)d_in[0];
    const float* x_pos = (const float*)d_in[1];
    const float* wq = (const float*)d_in[2];  const float* bq = (const float*)d_in[3];
    const float* wk = (const float*)d_in[4];  const float* bk = (const float*)d_in[5];
    const float* wv = (const float*)d_in[6];  const float* bv = (const float*)d_in[7];
    const float* wc = (const float*)d_in[8];  const float* bc = (const float*)d_in[9];
    const float* w1 = (const float*)d_in[10]; const float* b1 = (const float*)d_in[11];
    const float* w2 = (const float*)d_in[12]; const float* b2 = (const float*)d_in[13];
    const float* g1 = (const float*)d_in[14]; const float* be1 = (const float*)d_in[15];
    const float* g2 = (const float*)d_in[16]; const float* be2 = (const float*)d_in[17];
    float* out = (float*)d_out;

    float *gx, *gq, *gk, *gv, *gproj, *ga, *gffn;
    bf16 *gxh, *gxl, *gath, *gatl, *gah, *gal, *gh1h, *gh1l;
    bf16 *wqh, *wql, *wkh, *wkl, *wvh, *wvl, *wch, *wcl, *w1h, *w1l, *w2h, *w2l;
    cudaGetSymbolAddress((void**)&gx,   g_x);
    cudaGetSymbolAddress((void**)&gxh,  g_xh);
    cudaGetSymbolAddress((void**)&gxl,  g_xl);
    cudaGetSymbolAddress((void**)&wqh,  g_wqh); cudaGetSymbolAddress((void**)&wql, g_wql);
    cudaGetSymbolAddress((void**)&wkh,  g_wkh); cudaGetSymbolAddress((void**)&wkl, g_wkl);
    cudaGetSymbolAddress((void**)&wvh,  g_wvh); cudaGetSymbolAddress((void**)&wvl, g_wvl);
    cudaGetSymbolAddress((void**)&wch,  g_wch); cudaGetSymbolAddress((void**)&wcl, g_wcl);
    cudaGetSymbolAddress((void**)&w1h,  g_w1h); cudaGetSymbolAddress((void**)&w1l, g_w1l);
    cudaGetSymbolAddress((void**)&w2h,  g_w2h); cudaGetSymbolAddress((void**)&w2l, g_w2l);
    cudaGetSymbolAddress((void**)&gq,   g_q);
    cudaGetSymbolAddress((void**)&gk,   g_k);
    cudaGetSymbolAddress((void**)&gv,   g_v);
    cudaGetSymbolAddress((void**)&gath, g_ath); cudaGetSymbolAddress((void**)&gatl, g_atl);
    cudaGetSymbolAddress((void**)&gproj, g_proj);
    cudaGetSymbolAddress((void**)&ga,   g_a);
    cudaGetSymbolAddress((void**)&gah,  g_ah);  cudaGetSymbolAddress((void**)&gal, g_al);
    cudaGetSymbolAddress((void**)&gh1h, g_h1h); cudaGetSymbolAddress((void**)&gh1l, g_h1l);
    cudaGetSymbolAddress((void**)&gffn, g_ffn);

    cudaFuncSetAttribute(gemm_tc, cudaFuncAttributeMaxDynamicSharedMemorySize, GEMM_SMEM);
    cudaFuncSetAttribute(flash_attn_kernel, cudaFuncAttributeMaxDynamicSharedMemorySize, AT_SMEM);

    // x = x_enc + x_pos (+ hi/lo split)
    const int n4 = NTOK * Dm / 4;
    add_convert<<<n4 / 256, 256>>>(x_enc, x_pos, gx, gxh, gxl, n4);

    // weight transpose + split
    dim3 tb(32, 8);
    wconvert_t<<<dim3(Dm/32, Dm/32), tb>>>(wq, wqh, wql, Dm, Dm);
    wconvert_t<<<dim3(Dm/32, Dm/32), tb>>>(wk, wkh, wkl, Dm, Dm);
    wconvert_t<<<dim3(Dm/32, Dm/32), tb>>>(wv, wvh, wvl, Dm, Dm);
    wconvert_t<<<dim3(Dm/32, Dm/32), tb>>>(wc, wch, wcl, Dm, Dm);
    wconvert_t<<<dim3(Ff/32, Dm/32), tb>>>(w1, w1h, w1l, Dm, Ff);
    wconvert_t<<<dim3(Dm/32, Ff/32), tb>>>(w2, w2h, w2l, Ff, Dm);

    auto launch_gemm = [&](const bf16* Ah, const bf16* Al, const bf16* Bh, const bf16* Bl,
                           const float* bias, float* Cf, bf16* Ch, bf16* Cl,
                           int M, int N, int K, int relu) {
        dim3 grid(N / TBN, M / TBM);
        gemm_tc<<<grid, 256, GEMM_SMEM>>>(
            (const uint4*)Ah, (const uint4*)Al, (const uint4*)Bh, (const uint4*)Bl,
            bias, Cf, Ch, Cl, M, N, K, relu);
    };

    // QKV projections
    launch_gemm(gxh, gxl, wqh, wql, bq, gq, nullptr, nullptr, NTOK, Dm, Dm, 0);
    launch_gemm(gxh, gxl, wkh, wkl, bk, gk, nullptr, nullptr, NTOK, Dm, Dm, 0);
    launch_gemm(gxh, gxl, wvh, wvl, bv, gv, nullptr, nullptr, NTOK, Dm, Dm, 0);

    // attention -> bf16 hi/lo
    flash_attn_kernel<<<dim3(Sq / 64, Bsz * Hh), 256, AT_SMEM>>>(gq, gk, gv, gath, gatl);

    // output projection
    launch_gemm(gath, gatl, wch, wcl, bc, gproj, nullptr, nullptr, NTOK, Dm, Dm, 0);

    // a = x + LN(proj)  (+ hi/lo)
    ln_residual_kernel<<<NTOK, 256>>>(gx, gproj, g1, be1, ga, gah, gal);

    // FFN
    launch_gemm(gah, gal, w1h, w1l, b1, nullptr, gh1h, gh1l, NTOK, Ff, Dm, 1);
    launch_gemm(gh1h, gh1l, w2h, w2l, b2, gffn, nullptr, nullptr, NTOK, Dm, Ff, 0);

    // out = a + LN(ffn)
    ln_residual_kernel<<<NTOK, 256>>>(ga, gffn, g2, be2, out, nullptr, nullptr);
}

// round 4
// speedup vs baseline: 3.3049x; 1.5685x over previous
#include <cuda_runtime.h>
#include <cuda_bf16.h>
#include <cstdint>
#include <math.h>

#define Bsz 2
#define Sq 2048
#define Dm 1024
#define Hh 16
#define DHd 64
#define Ff 4096
#define NTOK (Bsz*Sq)

typedef __nv_bfloat16 bf16;

#if defined(__CUDA_ARCH__) && (defined(__CUDA_ARCH_FEAT_SM103_ALL) || defined(__CUDA_ARCH_FEAT_SM100_ALL) || (defined(__CUDA_ARCH_SPECIFIC__) && (__CUDA_ARCH_SPECIFIC__ >= 1000)))
#define USE_TCGEN05 1
#else
#define USE_TCGEN05 0
#endif

// ---------------- scratch (device globals) ------------------------------------
__device__ float g_x[(size_t)NTOK*Dm];
__device__ bf16  g_xh[(size_t)NTOK*Dm];
__device__ bf16  g_xl[(size_t)NTOK*Dm];

__device__ bf16 g_wqh[(size_t)Dm*Dm], g_wql[(size_t)Dm*Dm];
__device__ bf16 g_wkh[(size_t)Dm*Dm], g_wkl[(size_t)Dm*Dm];
__device__ bf16 g_wvh[(size_t)Dm*Dm], g_wvl[(size_t)Dm*Dm];
__device__ bf16 g_wch[(size_t)Dm*Dm], g_wcl[(size_t)Dm*Dm];
__device__ bf16 g_w1h[(size_t)Ff*Dm], g_w1l[(size_t)Ff*Dm];
__device__ bf16 g_w2h[(size_t)Dm*Ff], g_w2l[(size_t)Dm*Ff];

__device__ bf16 g_qh[(size_t)NTOK*Dm], g_ql[(size_t)NTOK*Dm];
__device__ bf16 g_kh[(size_t)NTOK*Dm], g_kl[(size_t)NTOK*Dm];
__device__ bf16 g_vh[(size_t)NTOK*Dm], g_vl[(size_t)NTOK*Dm];
__device__ bf16  g_ath[(size_t)NTOK*Dm], g_atl[(size_t)NTOK*Dm];
__device__ float g_proj[(size_t)NTOK*Dm];
__device__ float g_a[(size_t)NTOK*Dm];
__device__ bf16  g_ah[(size_t)NTOK*Dm], g_al[(size_t)NTOK*Dm];
__device__ bf16  g_h1h[(size_t)NTOK*Ff], g_h1l[(size_t)NTOK*Ff];
__device__ float g_ffn[(size_t)NTOK*Dm];

// ---------------- common helpers ----------------------------------------------
__device__ __forceinline__ uint32_t smem_u32(const void* p){
    uint32_t a;
    asm("{ .reg .u64 t; cvta.to.shared.u64 t, %1; cvt.u32.u64 %0, t; }" : "=r"(a) : "l"(p));
    return a;
}
#define SWZ(x) ((x) ^ (((x) >> 3) & 0x70))

__device__ __forceinline__ void split2(float v, bf16& h, bf16& l){
    h = __float2bfloat16(v);
    l = __float2bfloat16(v - __bfloat162float(h));
}
__device__ __forceinline__ uint32_t pack_bf2(float a, float b){
    __nv_bfloat162 t = __floats2bfloat162_rn(a, b);
    return *(uint32_t*)&t;
}

// legacy tensor-core helpers (legal on family-generic sm_103 and sm_103a)
__device__ __forceinline__ void ldsm_x4(uint32_t& r0, uint32_t& r1, uint32_t& r2,
                                        uint32_t& r3, uint32_t addr){
    asm volatile("ldmatrix.sync.aligned.m8n8.x4.shared.b16 {%0,%1,%2,%3}, [%4];"
                 : "=r"(r0), "=r"(r1), "=r"(r2), "=r"(r3) : "r"(addr));
}
__device__ __forceinline__ void ldsm_x4_t(uint32_t& r0, uint32_t& r1, uint32_t& r2,
                                          uint32_t& r3, uint32_t addr){
    asm volatile("ldmatrix.sync.aligned.m8n8.x4.trans.shared.b16 {%0,%1,%2,%3}, [%4];"
                 : "=r"(r0), "=r"(r1), "=r"(r2), "=r"(r3) : "r"(addr));
}
__device__ __forceinline__ void mma16816(float* c, const uint32_t* a, const uint32_t* b){
    asm volatile(
        "mma.sync.aligned.m16n8k16.row.col.f32.bf16.bf16.f32 "
        "{%0,%1,%2,%3}, {%4,%5,%6,%7}, {%8,%9}, {%0,%1,%2,%3};"
        : "+f"(c[0]), "+f"(c[1]), "+f"(c[2]), "+f"(c[3])
        : "r"(a[0]), "r"(a[1]), "r"(a[2]), "r"(a[3]), "r"(b[0]), "r"(b[1]));
}

// FMA-pipe 2^t for t <= 0 (avoids MUFU bottleneck)
__device__ __forceinline__ float exp2p(float t){
    t = fmaxf(t, -100.f);
    float n = t + 12582912.f;          // round-to-nearest-int via magic
    n -= 12582912.f;
    float f = t - n;
    float fl = f * 0.6931471805599453f;
    float p = fmaf(fl, fmaf(fl, fmaf(fl, fmaf(fl, fmaf(fl, 0.0083333333f,
              0.0416666667f), 0.1666666667f), 0.5f), 1.f), 1.f);
    return __uint_as_float((uint32_t)((int)n + 127) << 23) * p;
}

#if USE_TCGEN05
__device__ __forceinline__ uint32_t elect_one(){
    uint32_t p;
    asm volatile("{\n\t.reg .pred p;\n\telect.sync _|p, 0xFFFFFFFF;\n\tselp.b32 %0, 1, 0, p;\n\t}" : "=r"(p));
    return p;
}
__device__ __forceinline__ uint64_t make_desc(uint32_t addr){
    return ((uint64_t)2 << 61) | ((uint64_t)1 << 46) | ((uint64_t)64 << 32)
         | ((uint64_t)1 << 16) | ((uint64_t)(addr >> 4) & 0x3FFF);
}
__device__ __forceinline__ void mma_f16_ss(uint32_t d, uint64_t a, uint64_t b,
                                           uint32_t idesc, uint32_t en){
    asm volatile(
        "{\n\t.reg .pred p;\n\tsetp.ne.u32 p, %4, 0;\n\t"
        "tcgen05.mma.cta_group::1.kind::f16 [%0], %1, %2, %3, {%5,%5,%5,%5}, p;\n\t}"
        :: "r"(d), "l"(a), "l"(b), "r"(idesc), "r"(en), "r"(0u) : "memory");
}
__device__ __forceinline__ void mbar_wait(uint32_t mbar, int parity){
    asm volatile(
        "{\n\t.reg .pred P;\n\t"
        "WL_%=:\n\t"
        "mbarrier.try_wait.parity.acquire.cta.shared::cta.b64 P, [%0], %1, 0x989680;\n\t"
        "@P bra.uni WD_%=;\n\t"
        "bra.uni WL_%=;\n\t"
        "WD_%=:\n\t}"
        :: "r"(mbar), "r"(parity) : "memory");
}
#define LDTM_X32(r, addr) \
    asm volatile( \
        "tcgen05.ld.sync.aligned.32x32b.x32.b32 " \
        "{%0, %1, %2, %3, %4, %5, %6, %7, " \
        " %8, %9, %10, %11, %12, %13, %14, %15, " \
        " %16, %17, %18, %19, %20, %21, %22, %23, " \
        " %24, %25, %26, %27, %28, %29, %30, %31}, [%32];" \
        : "=r"((r)[0]),  "=r"((r)[1]),  "=r"((r)[2]),  "=r"((r)[3]), \
          "=r"((r)[4]),  "=r"((r)[5]),  "=r"((r)[6]),  "=r"((r)[7]), \
          "=r"((r)[8]),  "=r"((r)[9]),  "=r"((r)[10]), "=r"((r)[11]), \
          "=r"((r)[12]), "=r"((r)[13]), "=r"((r)[14]), "=r"((r)[15]), \
          "=r"((r)[16]), "=r"((r)[17]), "=r"((r)[18]), "=r"((r)[19]), \
          "=r"((r)[20]), "=r"((r)[21]), "=r"((r)[22]), "=r"((r)[23]), \
          "=r"((r)[24]), "=r"((r)[25]), "=r"((r)[26]), "=r"((r)[27]), \
          "=r"((r)[28]), "=r"((r)[29]), "=r"((r)[30]), "=r"((r)[31]) \
        : "r"(addr))
#endif

// ---------------- x = a + b, emit fp32 + bf16 hi/lo ---------------------------
__global__ __launch_bounds__(256) void add_convert(
    const float* __restrict__ a, const float* __restrict__ b,
    float* __restrict__ o, bf16* __restrict__ oh, bf16* __restrict__ ol, int n4)
{
    int i = blockIdx.x * 256 + threadIdx.x;
    if (i >= n4) return;
    float4 av = ((const float4*)a)[i];
    float4 bv = ((const float4*)b)[i];
    float4 v;
    v.x = av.x + bv.x; v.y = av.y + bv.y; v.z = av.z + bv.z; v.w = av.w + bv.w;
    ((float4*)o)[i] = v;
    bf16 h[4], l[4];
    split2(v.x, h[0], l[0]); split2(v.y, h[1], l[1]);
    split2(v.z, h[2], l[2]); split2(v.w, h[3], l[3]);
    *(uint2*)(oh + (size_t)i * 4) = *(uint2*)h;
    *(uint2*)(ol + (size_t)i * 4) = *(uint2*)l;
}

// ---------------- weight transpose + split ------------------------------------
__global__ __launch_bounds__(256) void wconvert_t(
    const float* __restrict__ W, bf16* __restrict__ Th, bf16* __restrict__ Tl,
    int K, int N)
{
    __shared__ float t[32][33];
    int n0 = blockIdx.x * 32, k0 = blockIdx.y * 32;
    int x = threadIdx.x, y = threadIdx.y;
    #pragma unroll
    for (int i = 0; i < 4; i++)
        t[y + 8*i][x] = W[(size_t)(k0 + y + 8*i) * N + n0 + x];
    __syncthreads();
    #pragma unroll
    for (int i = 0; i < 4; i++) {
        float v = t[x][y + 8*i];
        bf16 h, l; split2(v, h, l);
        size_t idx = (size_t)(n0 + y + 8*i) * K + k0 + x;
        Th[idx] = h; Tl[idx] = l;
    }
}

// ---------------- bf16x3 GEMM (same as round 3) -------------------------------
#define TBM 128
#define TBN 128
#define TBK 64
#define STG 65536
#define SM_BASE 1024
#define GEMM_SMEM (SM_BASE + 2*STG)

__global__ __launch_bounds__(256, 1) void gemm_tc(
    const uint4* __restrict__ Ah4, const uint4* __restrict__ Al4,
    const uint4* __restrict__ Bh4, const uint4* __restrict__ Bl4,
    const float* __restrict__ bias,
    float* __restrict__ Cf, bf16* __restrict__ Ch, bf16* __restrict__ Cl,
    int M, int N, int K, int relu)
{
    extern __shared__ char smbuf[];
    const int tid = threadIdx.x;
    const int wid = tid >> 5;
    const int lane = tid & 31;
    const uint32_t sbase = smem_u32(smbuf);

    const int rowBase = blockIdx.y * TBM;
    const int colBase = blockIdx.x * TBN;
    const int K8 = K >> 3;
    const int nch = K / TBK;

    uint4 pf[16];
    auto ldg_stage = [&](int i){
        const int kc8 = i * 8;
        #pragma unroll
        for (int t = 0; t < 4; t++) {
            int id = tid + t * 256;
            int r = id >> 3, c = id & 7;
            size_t goA = (size_t)(rowBase + r) * K8 + kc8 + c;
            size_t goB = (size_t)(colBase + r) * K8 + kc8 + c;
            pf[t]      = Ah4[goA];
            pf[4 + t]  = Al4[goA];
            pf[8 + t]  = Bh4[goB];
            pf[12 + t] = Bl4[goB];
        }
    };
    auto sts_stage = [&](int buf){
        char* st = smbuf + SM_BASE + buf * STG;
        #pragma unroll
        for (int t = 0; t < 4; t++) {
            int id = tid + t * 256;
            int r = id >> 3, c = id & 7;
            uint32_t sw = SWZ(r * 128 + c * 16);
            *(uint4*)(st + sw)          = pf[t];
            *(uint4*)(st + 16384 + sw)  = pf[4 + t];
            *(uint4*)(st + 32768 + sw)  = pf[8 + t];
            *(uint4*)(st + 49152 + sw)  = pf[12 + t];
        }
    };

#if USE_TCGEN05
    if (wid == 0)
        asm volatile("tcgen05.alloc.cta_group::1.sync.aligned.shared::cta.b32 [%0], %1;"
                     :: "r"(sbase), "r"(128) : "memory");
    if (tid == 0) {
        asm volatile("mbarrier.init.shared.b64 [%0], 1;" :: "r"(sbase + 16) : "memory");
        asm volatile("mbarrier.init.shared.b64 [%0], 1;" :: "r"(sbase + 24) : "memory");
    }
    __syncthreads();
    uint32_t tmem;
    asm volatile("ld.shared.b32 %0, [%1];" : "=r"(tmem) : "r"(sbase));

    uint64_t dAh[2], dAl[2], dBh[2], dBl[2];
    #pragma unroll
    for (int s = 0; s < 2; s++) {
        uint32_t b = sbase + SM_BASE + s * STG;
        dAh[s] = make_desc(b);
        dAl[s] = make_desc(b + 16384);
        dBh[s] = make_desc(b + 32768);
        dBl[s] = make_desc(b + 49152);
    }
    const uint32_t IDESC = (1u<<4) | (1u<<7) | (1u<<10) | (16u<<17) | (8u<<24);

    ldg_stage(0);
    sts_stage(0);
    asm volatile("fence.proxy.async.shared::cta;" ::: "memory");
    __syncthreads();

    int ph[2] = {0, 0};
    for (int i = 0; i < nch; i++) {
        const int s = i & 1;
        if (wid == 0 && elect_one()) {
            #pragma unroll
            for (int k = 0; k < 4; k++) {
                uint64_t oa = (uint64_t)(k * 2);
                uint32_t en0 = (i == 0 && k == 0) ? 0u : 1u;
                mma_f16_ss(tmem, dAh[s] + oa, dBh[s] + oa, IDESC, en0);
                mma_f16_ss(tmem, dAh[s] + oa, dBl[s] + oa, IDESC, 1u);
                mma_f16_ss(tmem, dAl[s] + oa, dBh[s] + oa, IDESC, 1u);
            }
            asm volatile(
                "tcgen05.commit.cta_group::1.mbarrier::arrive::one.shared::cluster.b64 [%0];"
                :: "r"(sbase + 16 + s * 8) : "memory");
        }
        if (i + 1 < nch) {
            ldg_stage(i + 1);
            const int s2 = (i + 1) & 1;
            if (i >= 1) { mbar_wait(sbase + 16 + s2 * 8, ph[s2]); ph[s2] ^= 1; }
            sts_stage(s2);
            asm volatile("fence.proxy.async.shared::cta;" ::: "memory");
        }
        __syncthreads();
    }
    { const int s2 = (nch - 2) & 1; mbar_wait(sbase + 16 + s2 * 8, ph[s2]); ph[s2] ^= 1; }
    { const int s2 = (nch - 1) & 1; mbar_wait(sbase + 16 + s2 * 8, ph[s2]); ph[s2] ^= 1; }
    asm volatile("tcgen05.fence::after_thread_sync;" ::: "memory");

    if (wid < 4) {
        const int row = rowBase + wid * 32 + lane;
        #pragma unroll
        for (int cc = 0; cc < 128; cc += 32) {
            uint32_t dr[32];
            LDTM_X32(dr, tmem + cc);
            asm volatile("tcgen05.wait::ld.sync.aligned;" ::: "memory");
            int col = colBase + cc;
            float v[32];
            #pragma unroll
            for (int j = 0; j < 32; j++) {
                v[j] = __uint_as_float(dr[j]) + bias[col + j];
                if (relu) v[j] = fmaxf(v[j], 0.f);
            }
            if (Cf) {
                #pragma unroll
                for (int j = 0; j < 32; j += 4) {
                    float4 o4 = {v[j], v[j+1], v[j+2], v[j+3]};
                    *(float4*)(Cf + (size_t)row * N + col + j) = o4;
                }
            }
            if (Ch) {
                bf16 hv[32], lv[32];
                #pragma unroll
                for (int j = 0; j < 32; j++) split2(v[j], hv[j], lv[j]);
                #pragma unroll
                for (int j = 0; j < 32; j += 8) {
                    *(uint4*)(Ch + (size_t)row * N + col + j) = *(uint4*)(hv + j);
                    *(uint4*)(Cl + (size_t)row * N + col + j) = *(uint4*)(lv + j);
                }
            }
        }
    }
    __syncthreads();
    if (wid == 0)
        asm volatile("tcgen05.dealloc.cta_group::1.sync.aligned.b32 %0, %1;"
                     :: "r"(tmem), "r"(128));
#else
    const int wm = (wid & 1) * 64;
    const int wn = (wid >> 1) * 32;

    float acc[4][4][4];
    #pragma unroll
    for (int mt = 0; mt < 4; mt++)
        #pragma unroll
        for (int nt = 0; nt < 4; nt++)
            #pragma unroll
            for (int e = 0; e < 4; e++) acc[mt][nt][e] = 0.f;

    auto compute = [&](int buf){
        const uint32_t ab = sbase + SM_BASE + buf * STG;
        #pragma unroll
        for (int ks = 0; ks < 4; ks++) {
            const int kb = ks * 32;
            uint32_t ah[4][4], al[4][4], bh[2][4], bl[2][4];
            #pragma unroll
            for (int mt = 0; mt < 4; mt++) {
                uint32_t off = SWZ((wm + mt*16 + (lane & 15)) * 128 + kb + (lane >> 4) * 16);
                ldsm_x4(ah[mt][0], ah[mt][1], ah[mt][2], ah[mt][3], ab + off);
                ldsm_x4(al[mt][0], al[mt][1], al[mt][2], al[mt][3], ab + 16384 + off);
            }
            #pragma unroll
            for (int p = 0; p < 2; p++) {
                uint32_t off = SWZ((wn + p*16 + (lane & 15)) * 128 + kb + (lane >> 4) * 16);
                ldsm_x4(bh[p][0], bh[p][1], bh[p][2], bh[p][3], ab + 32768 + off);
                ldsm_x4(bl[p][0], bl[p][1], bl[p][2], bl[p][3], ab + 49152 + off);
            }
            #pragma unroll
            for (int mt = 0; mt < 4; mt++) {
                #pragma unroll
                for (int nt = 0; nt < 4; nt++) {
                    uint32_t fh[2] = { bh[nt >> 1][nt & 1], bh[nt >> 1][2 + (nt & 1)] };
                    uint32_t fl[2] = { bl[nt >> 1][nt & 1], bl[nt >> 1][2 + (nt & 1)] };
                    mma16816(acc[mt][nt], ah[mt], fh);
                    mma16816(acc[mt][nt], ah[mt], fl);
                    mma16816(acc[mt][nt], al[mt], fh);
                }
            }
        }
    };

    ldg_stage(0);
    sts_stage(0);
    __syncthreads();
    for (int i = 0; i < nch; i++) {
        const bool more = (i + 1 < nch);
        if (more) ldg_stage(i + 1);
        compute(i & 1);
        if (more) sts_stage((i + 1) & 1);
        __syncthreads();
    }

    #pragma unroll
    for (int mt = 0; mt < 4; mt++) {
        #pragma unroll
        for (int nt = 0; nt < 4; nt++) {
            int r0 = rowBase + wm + mt*16 + (lane >> 2);
            int c0 = colBase + wn + nt*8 + (lane & 3) * 2;
            float2 bb = *(const float2*)(bias + c0);
            #pragma unroll
            for (int half = 0; half < 2; half++) {
                int r = r0 + half * 8;
                float vx = acc[mt][nt][half*2 + 0] + bb.x;
                float vy = acc[mt][nt][half*2 + 1] + bb.y;
                if (relu) { vx = fmaxf(vx, 0.f); vy = fmaxf(vy, 0.f); }
                if (Cf) {
                    float2 o2 = {vx, vy};
                    *(float2*)(Cf + (size_t)r * N + c0) = o2;
                }
                if (Ch) {
                    bf16 hx, lx, hy, ly;
                    split2(vx, hx, lx); split2(vy, hy, ly);
                    bf16 hp[2] = {hx, hy}, lp[2] = {lx, ly};
                    *(uint32_t*)(Ch + (size_t)r * N + c0) = *(uint32_t*)hp;
                    *(uint32_t*)(Cl + (size_t)r * N + c0) = *(uint32_t*)lp;
                }
            }
        }
    }
#endif
}

// ---------------- tensor-core flash attention ---------------------------------
// grid (Sq/128, B*H), 256 threads (8 warps, 16 q-rows each). 128 kv per tile.
// smem: Qh 0, Ql 16K, Kh 32K, Kl 48K, Vh 64K, Vl 80K (all 128rows x 128B, SW128)
#define FA_SMEM 98304
#define L2S 0.1803368801111f   // 0.125 * log2(e)

__global__ __launch_bounds__(256, 1) void flash_attn_tc(
    const uint4* __restrict__ Qh4, const uint4* __restrict__ Ql4,
    const uint4* __restrict__ Kh4, const uint4* __restrict__ Kl4,
    const uint4* __restrict__ Vh4, const uint4* __restrict__ Vl4,
    bf16* __restrict__ Oh, bf16* __restrict__ Ol)
{
    extern __shared__ char sm[];
    const uint32_t sb = smem_u32(sm);
    const int tid = threadIdx.x;
    const int wid = tid >> 5;
    const int lane = tid & 31;
    const int bh = blockIdx.y;
    const int b = bh >> 4, h = bh & 15;
    const int q0 = blockIdx.x * 128;

    // load Q (hi/lo) into smem
    #pragma unroll
    for (int t = 0; t < 4; t++) {
        int id = tid + t * 256;
        int r = id >> 3, c = id & 7;
        size_t src = (size_t)(b * Sq + q0 + r) * 128 + h * 8 + c;
        uint32_t sw = SWZ(r * 128 + c * 16);
        *(uint4*)(sm + sw)          = Qh4[src];
        *(uint4*)(sm + 16384 + sw)  = Ql4[src];
    }
    __syncthreads();

    // hoist Q fragments
    uint32_t qh[4][4], ql[4][4];
    #pragma unroll
    for (int ks = 0; ks < 4; ks++) {
        uint32_t loc = SWZ((wid * 16 + (lane & 15)) * 128 + ks * 32 + (lane >> 4) * 16);
        ldsm_x4(qh[ks][0], qh[ks][1], qh[ks][2], qh[ks][3], sb + loc);
        ldsm_x4(ql[ks][0], ql[ks][1], ql[ks][2], ql[ks][3], sb + 16384 + loc);
    }

    float o[8][4];
    #pragma unroll
    for (int u = 0; u < 8; u++)
        #pragma unroll
        for (int e = 0; e < 4; e++) o[u][e] = 0.f;
    float m0 = -1e30f, m1 = -1e30f, l0 = 0.f, l1 = 0.f;

    for (int j0 = 0; j0 < Sq; j0 += 128) {
        __syncthreads();
        #pragma unroll
        for (int t = 0; t < 4; t++) {
            int id = tid + t * 256;
            int r = id >> 3, c = id & 7;
            size_t src = (size_t)(b * Sq + j0 + r) * 128 + h * 8 + c;
            uint32_t sw = SWZ(r * 128 + c * 16);
            *(uint4*)(sm + 32768 + sw) = Kh4[src];
            *(uint4*)(sm + 49152 + sw) = Kl4[src];
            *(uint4*)(sm + 65536 + sw) = Vh4[src];
            *(uint4*)(sm + 81920 + sw) = Vl4[src];
        }
        __syncthreads();

        // S = QK^T (bf16x3)
        float s[16][4];
        #pragma unroll
        for (int t = 0; t < 16; t++)
            #pragma unroll
            for (int e = 0; e < 4; e++) s[t][e] = 0.f;

        #pragma unroll
        for (int nc = 0; nc < 8; nc++) {
            #pragma unroll
            for (int ks = 0; ks < 4; ks++) {
                uint32_t kh[4], kl[4];
                uint32_t loc = SWZ((nc * 16 + (lane & 15)) * 128 + ks * 32 + (lane >> 4) * 16);
                ldsm_x4(kh[0], kh[1], kh[2], kh[3], sb + 32768 + loc);
                ldsm_x4(kl[0], kl[1], kl[2], kl[3], sb + 49152 + loc);
                uint32_t bh0[2] = {kh[0], kh[2]}, bh1[2] = {kh[1], kh[3]};
                uint32_t bl0[2] = {kl[0], kl[2]}, bl1[2] = {kl[1], kl[3]};
                mma16816(s[2*nc],   qh[ks], bh0);
                mma16816(s[2*nc+1], qh[ks], bh1);
                mma16816(s[2*nc],   qh[ks], bl0);
                mma16816(s[2*nc+1], qh[ks], bl1);
                mma16816(s[2*nc],   ql[ks], bh0);
                mma16816(s[2*nc+1], ql[ks], bh1);
            }
        }

        // online softmax (rows r0 = lane>>2, r1 = r0+8)
        float mx0 = -1e30f, mx1 = -1e30f;
        #pragma unroll
        for (int t = 0; t < 16; t++) {
            mx0 = fmaxf(mx0, fmaxf(s[t][0], s[t][1]));
            mx1 = fmaxf(mx1, fmaxf(s[t][2], s[t][3]));
        }
        mx0 = fmaxf(mx0, __shfl_xor_sync(0xffffffffu, mx0, 1));
        mx0 = fmaxf(mx0, __shfl_xor_sync(0xffffffffu, mx0, 2));
        mx1 = fmaxf(mx1, __shfl_xor_sync(0xffffffffu, mx1, 1));
        mx1 = fmaxf(mx1, __shfl_xor_sync(0xffffffffu, mx1, 2));
        float mn0 = fmaxf(m0, mx0), mn1 = fmaxf(m1, mx1);
        float c0 = exp2p((m0 - mn0) * L2S);
        float c1 = exp2p((m1 - mn1) * L2S);
        m0 = mn0; m1 = mn1;

        float sum0 = 0.f, sum1 = 0.f;
        uint32_t pA[16], pB[16], plA[16], plB[16];
        #pragma unroll
        for (int t = 0; t < 16; t++) {
            float p0 = exp2p((s[t][0] - mn0) * L2S);
            float p1 = exp2p((s[t][1] - mn0) * L2S);
            float p2 = exp2p((s[t][2] - mn1) * L2S);
            float p3 = exp2p((s[t][3] - mn1) * L2S);
            sum0 += p0 + p1;
            sum1 += p2 + p3;
            pA[t] = pack_bf2(p0, p1);
            pB[t] = pack_bf2(p2, p3);
            __nv_bfloat162 hA = *(__nv_bfloat162*)&pA[t];
            __nv_bfloat162 hB = *(__nv_bfloat162*)&pB[t];
            plA[t] = pack_bf2(p0 - __bfloat162float(hA.x), p1 - __bfloat162float(hA.y));
            plB[t] = pack_bf2(p2 - __bfloat162float(hB.x), p3 - __bfloat162float(hB.y));
        }
        sum0 += __shfl_xor_sync(0xffffffffu, sum0, 1);
        sum0 += __shfl_xor_sync(0xffffffffu, sum0, 2);
        sum1 += __shfl_xor_sync(0xffffffffu, sum1, 1);
        sum1 += __shfl_xor_sync(0xffffffffu, sum1, 2);
        l0 = l0 * c0 + sum0;
        l1 = l1 * c1 + sum1;
        #pragma unroll
        for (int u = 0; u < 8; u++) {
            o[u][0] *= c0; o[u][1] *= c0;
            o[u][2] *= c1; o[u][3] *= c1;
        }

        // O += P @ V (bf16x3)
        #pragma unroll
        for (int j = 0; j < 8; j++) {
            uint32_t ah[4] = {pA[2*j], pB[2*j], pA[2*j+1], pB[2*j+1]};
            uint32_t al[4] = {plA[2*j], plB[2*j], plA[2*j+1], plB[2*j+1]};
            #pragma unroll
            for (int p = 0; p < 4; p++) {
                uint32_t vh[4], vl[4];
                uint32_t loc = SWZ((j * 16 + (lane & 15)) * 128 + p * 32 + (lane >> 4) * 16);
                ldsm_x4_t(vh[0], vh[1], vh[2], vh[3], sb + 65536 + loc);
                ldsm_x4_t(vl[0], vl[1], vl[2], vl[3], sb + 81920 + loc);
                uint32_t bh0[2] = {vh[0], vh[1]}, bh1[2] = {vh[2], vh[3]};
                uint32_t bl0[2] = {vl[0], vl[1]}, bl1[2] = {vl[2], vl[3]};
                mma16816(o[2*p],   ah, bh0);
                mma16816(o[2*p+1], ah, bh1);
                mma16816(o[2*p],   ah, bl0);
                mma16816(o[2*p+1], ah, bl1);
                mma16816(o[2*p],   al, bh0);
                mma16816(o[2*p+1], al, bh1);
            }
        }
    }

    // normalize + write bf16 hi/lo
    float inv0 = 1.f / l0, inv1 = 1.f / l1;
    int r0 = q0 + wid * 16 + (lane >> 2);
    int r1 = r0 + 8;
    #pragma unroll
    for (int u = 0; u < 8; u++) {
        int col = h * 64 + u * 8 + (lane & 3) * 2;
        float v0 = o[u][0] * inv0, v1 = o[u][1] * inv0;
        float v2 = o[u][2] * inv1, v3 = o[u][3] * inv1;
        uint32_t h0 = pack_bf2(v0, v1), h1p = pack_bf2(v2, v3);
        __nv_bfloat162 hh0 = *(__nv_bfloat162*)&h0;
        __nv_bfloat162 hh1 = *(__nv_bfloat162*)&h1p;
        uint32_t lo0 = pack_bf2(v0 - __bfloat162float(hh0.x), v1 - __bfloat162float(hh0.y));
        uint32_t lo1 = pack_bf2(v2 - __bfloat162float(hh1.x), v3 - __bfloat162float(hh1.y));
        *(uint32_t*)(Oh + (size_t)(b * Sq + r0) * Dm + col) = h0;
        *(uint32_t*)(Ol + (size_t)(b * Sq + r0) * Dm + col) = lo0;
        *(uint32_t*)(Oh + (size_t)(b * Sq + r1) * Dm + col) = h1p;
        *(uint32_t*)(Ol + (size_t)(b * Sq + r1) * Dm + col) = lo1;
    }
}

// ---------------- LayerNorm + residual -----------------------------------------
__global__ __launch_bounds__(256) void ln_residual_kernel(
    const float* __restrict__ res, const float* __restrict__ x,
    const float* __restrict__ g, const float* __restrict__ be,
    float* __restrict__ out, bf16* __restrict__ oh, bf16* __restrict__ ol)
{
    const int row = blockIdx.x;
    const int tid = threadIdx.x;
    const float* xr = x + (size_t)row * Dm;

    float4 v = *(const float4*)(xr + tid * 4);
    float s1 = v.x + v.y + v.z + v.w;
    float s2 = v.x * v.x + v.y * v.y + v.z * v.z + v.w * v.w;
    #pragma unroll
    for (int off = 16; off; off >>= 1) {
        s1 += __shfl_xor_sync(0xffffffffu, s1, off);
        s2 += __shfl_xor_sync(0xffffffffu, s2, off);
    }
    __shared__ float r1[8], r2[8];
    if ((tid & 31) == 0) { r1[tid >> 5] = s1; r2[tid >> 5] = s2; }
    __syncthreads();
    float t1 = 0.f, t2 = 0.f;
    #pragma unroll
    for (int w = 0; w < 8; w++) { t1 += r1[w]; t2 += r2[w]; }

    const float mu  = t1 * (1.f / Dm);
    const float var = t2 * (1.f / Dm) - mu * mu;
    const float rstd = rsqrtf(var + 1e-6f);

    float4 rv = *(const float4*)(res + (size_t)row * Dm + tid * 4);
    float4 gv = *(const float4*)(g + tid * 4);
    float4 bv = *(const float4*)(be + tid * 4);
    float4 ov;
    ov.x = rv.x + (v.x - mu) * rstd * gv.x + bv.x;
    ov.y = rv.y + (v.y - mu) * rstd * gv.y + bv.y;
    ov.z = rv.z + (v.z - mu) * rstd * gv.z + bv.z;
    ov.w = rv.w + (v.w - mu) * rstd * gv.w + bv.w;
    *(float4*)(out + (size_t)row * Dm + tid * 4) = ov;
    if (oh) {
        bf16 h[4], l[4];
        split2(ov.x, h[0], l[0]); split2(ov.y, h[1], l[1]);
        split2(ov.z, h[2], l[2]); split2(ov.w, h[3], l[3]);
        size_t idx = (size_t)row * Dm + tid * 4;
        *(uint2*)(oh + idx) = *(uint2*)h;
        *(uint2*)(ol + idx) = *(uint2*)l;
    }
}

// ---------------- launch --------------------------------------------------------
extern "C" void kernel_launch(void* const* d_in, const int* in_sizes, int n_in,
                              void* d_out, int out_size)
{
    const float* x_enc = (const float*)d_in[0];
    const float* x_pos = (const float*)d_in[1];
    const float* wq = (const float*)d_in[2];  const float* bq = (const float*)d_in[3];
    const float* wk = (const float*)d_in[4];  const float* bk = (const float*)d_in[5];
    const float* wv = (const float*)d_in[6];  const float* bv = (const float*)d_in[7];
    const float* wc = (const float*)d_in[8];  const float* bc = (const float*)d_in[9];
    const float* w1 = (const float*)d_in[10]; const float* b1 = (const float*)d_in[11];
    const float* w2 = (const float*)d_in[12]; const float* b2 = (const float*)d_in[13];
    const float* g1 = (const float*)d_in[14]; const float* be1 = (const float*)d_in[15];
    const float* g2 = (const float*)d_in[16]; const float* be2 = (const float*)d_in[17];
    float* out = (float*)d_out;

    float *gx, *gproj, *ga, *gffn;
    bf16 *gxh, *gxl, *gath, *gatl, *gah, *gal, *gh1h, *gh1l;
    bf16 *gqh, *gql, *gkh, *gkl, *gvh, *gvl;
    bf16 *wqh, *wql, *wkh, *wkl, *wvh, *wvl, *wch, *wcl, *w1h, *w1l, *w2h, *w2l;
    cudaGetSymbolAddress((void**)&gx,   g_x);
    cudaGetSymbolAddress((void**)&gxh,  g_xh);
    cudaGetSymbolAddress((void**)&gxl,  g_xl);
    cudaGetSymbolAddress((void**)&wqh,  g_wqh); cudaGetSymbolAddress((void**)&wql, g_wql);
    cudaGetSymbolAddress((void**)&wkh,  g_wkh); cudaGetSymbolAddress((void**)&wkl, g_wkl);
    cudaGetSymbolAddress((void**)&wvh,  g_wvh); cudaGetSymbolAddress((void**)&wvl, g_wvl);
    cudaGetSymbolAddress((void**)&wch,  g_wch); cudaGetSymbolAddress((void**)&wcl, g_wcl);
    cudaGetSymbolAddress((void**)&w1h,  g_w1h); cudaGetSymbolAddress((void**)&w1l, g_w1l);
    cudaGetSymbolAddress((void**)&w2h,  g_w2h); cudaGetSymbolAddress((void**)&w2l, g_w2l);
    cudaGetSymbolAddress((void**)&gqh,  g_qh);  cudaGetSymbolAddress((void**)&gql, g_ql);
    cudaGetSymbolAddress((void**)&gkh,  g_kh);  cudaGetSymbolAddress((void**)&gkl, g_kl);
    cudaGetSymbolAddress((void**)&gvh,  g_vh);  cudaGetSymbolAddress((void**)&gvl, g_vl);
    cudaGetSymbolAddress((void**)&gath, g_ath); cudaGetSymbolAddress((void**)&gatl, g_atl);
    cudaGetSymbolAddress((void**)&gproj, g_proj);
    cudaGetSymbolAddress((void**)&ga,   g_a);
    cudaGetSymbolAddress((void**)&gah,  g_ah);  cudaGetSymbolAddress((void**)&gal, g_al);
    cudaGetSymbolAddress((void**)&gh1h, g_h1h); cudaGetSymbolAddress((void**)&gh1l, g_h1l);
    cudaGetSymbolAddress((void**)&gffn, g_ffn);

    cudaFuncSetAttribute(gemm_tc, cudaFuncAttributeMaxDynamicSharedMemorySize, GEMM_SMEM);
    cudaFuncSetAttribute(flash_attn_tc, cudaFuncAttributeMaxDynamicSharedMemorySize, FA_SMEM);

    const int n4 = NTOK * Dm / 4;
    add_convert<<<n4 / 256, 256>>>(x_enc, x_pos, gx, gxh, gxl, n4);

    dim3 tb(32, 8);
    wconvert_t<<<dim3(Dm/32, Dm/32), tb>>>(wq, wqh, wql, Dm, Dm);
    wconvert_t<<<dim3(Dm/32, Dm/32), tb>>>(wk, wkh, wkl, Dm, Dm);
    wconvert_t<<<dim3(Dm/32, Dm/32), tb>>>(wv, wvh, wvl, Dm, Dm);
    wconvert_t<<<dim3(Dm/32, Dm/32), tb>>>(wc, wch, wcl, Dm, Dm);
    wconvert_t<<<dim3(Ff/32, Dm/32), tb>>>(w1, w1h, w1l, Dm, Ff);
    wconvert_t<<<dim3(Dm/32, Ff/32), tb>>>(w2, w2h, w2l, Ff, Dm);

    auto launch_gemm = [&](const bf16* Ah, const bf16* Al, const bf16* Bh, const bf16* Bl,
                           const float* bias, float* Cf, bf16* Ch, bf16* Cl,
                           int M, int N, int K, int relu) {
        dim3 grid(N / TBN, M / TBM);
        gemm_tc<<<grid, 256, GEMM_SMEM>>>(
            (const uint4*)Ah, (const uint4*)Al, (const uint4*)Bh, (const uint4*)Bl,
            bias, Cf, Ch, Cl, M, N, K, relu);
    };

    // QKV projections -> bf16 hi/lo for the tensor-core flash kernel
    launch_gemm(gxh, gxl, wqh, wql, bq, nullptr, gqh, gql, NTOK, Dm, Dm, 0);
    launch_gemm(gxh, gxl, wkh, wkl, bk, nullptr, gkh, gkl, NTOK, Dm, Dm, 0);
    launch_gemm(gxh, gxl, wvh, wvl, bv, nullptr, gvh, gvl, NTOK, Dm, Dm, 0);

    // tensor-core flash attention
    flash_attn_tc<<<dim3(Sq / 128, Bsz * Hh), 256, FA_SMEM>>>(
        (const uint4*)gqh, (const uint4*)gql, (const uint4*)gkh, (const uint4*)gkl,
        (const uint4*)gvh, (const uint4*)gvl, gath, gatl);

    // output projection
    launch_gemm(gath, gatl, wch, wcl, bc, gproj, nullptr, nullptr, NTOK, Dm, Dm, 0);

    // a = x + LN(proj)
    ln_residual_kernel<<<NTOK, 256>>>(gx, gproj, g1, be1, ga, gah, gal);

    // FFN
    launch_gemm(gah, gal, w1h, w1l, b1, nullptr, gh1h, gh1l, NTOK, Ff, Dm, 1);
    launch_gemm(gh1h, gh1l, w2h, w2l, b2, gffn, nullptr, nullptr, NTOK, Dm, Ff, 0);

    // out = a + LN(ffn)
    ln_residual_kernel<<<NTOK, 256>>>(ga, gffn, g2, be2, out, nullptr, nullptr);
}

// round 5
// speedup vs baseline: 3.4452x; 1.0424x over previous
#include <cuda_runtime.h>
#include <cuda_fp16.h>
#include <cstdint>
#include <math.h>

#define Bsz 2
#define Sq 2048
#define Dm 1024
#define Hh 16
#define DHd 64
#define Ff 4096
#define NTOK (Bsz*Sq)
#define NQKV 3072

typedef __half fp16;

// ---------------- scratch (device globals) ------------------------------------
__device__ float g_x[(size_t)NTOK*Dm];
__device__ fp16  g_xh[(size_t)NTOK*Dm];

__device__ fp16 g_wqkvh[(size_t)NQKV*Dm], g_wqkvl[(size_t)NQKV*Dm]; // [N=3K,K=D]
__device__ fp16 g_wch[(size_t)Dm*Dm], g_wcl[(size_t)Dm*Dm];
__device__ fp16 g_w1h[(size_t)Ff*Dm], g_w1l[(size_t)Ff*Dm];
__device__ fp16 g_w2h[(size_t)Dm*Ff], g_w2l[(size_t)Dm*Ff];
__device__ float g_bqkv[NQKV];

__device__ fp16 g_qkvh[(size_t)NTOK*NQKV], g_qkvl[(size_t)NTOK*NQKV];
__device__ fp16 g_ath[(size_t)NTOK*Dm];
__device__ float g_proj[(size_t)NTOK*Dm];
__device__ float g_a[(size_t)NTOK*Dm];
__device__ fp16  g_ah[(size_t)NTOK*Dm];
__device__ fp16  g_h1h[(size_t)NTOK*Ff];
__device__ float g_ffn[(size_t)NTOK*Dm];

// ---------------- helpers -------------------------------------------------------
__device__ __forceinline__ uint32_t smem_u32(const void* p){
    uint32_t a;
    asm("{ .reg .u64 t; cvta.to.shared.u64 t, %1; cvt.u32.u64 %0, t; }" : "=r"(a) : "l"(p));
    return a;
}
#define SWZ(x) ((x) ^ (((x) >> 3) & 0x70))

__device__ __forceinline__ void split2h(float v, fp16& h, fp16& l){
    h = __float2half_rn(v);
    l = __float2half_rn(v - __half2float(h));
}
__device__ __forceinline__ uint32_t pack_h2(float a, float b){
    __half2 t = __floats2half2_rn(a, b);
    return *(uint32_t*)&t;
}
__device__ __forceinline__ void cp16(uint32_t dst, const void* src){
    asm volatile("cp.async.cg.shared.global [%0], [%1], 16;" :: "r"(dst), "l"(src));
}
__device__ __forceinline__ void cp_commit(){
    asm volatile("cp.async.commit_group;" ::: "memory");
}
__device__ __forceinline__ void cp_wait1(){
    asm volatile("cp.async.wait_group 1;" ::: "memory");
}

__device__ __forceinline__ void ldsm_x4(uint32_t& r0, uint32_t& r1, uint32_t& r2,
                                        uint32_t& r3, uint32_t addr){
    asm volatile("ldmatrix.sync.aligned.m8n8.x4.shared.b16 {%0,%1,%2,%3}, [%4];"
                 : "=r"(r0), "=r"(r1), "=r"(r2), "=r"(r3) : "r"(addr));
}
__device__ __forceinline__ void ldsm_x4_t(uint32_t& r0, uint32_t& r1, uint32_t& r2,
                                          uint32_t& r3, uint32_t addr){
    asm volatile("ldmatrix.sync.aligned.m8n8.x4.trans.shared.b16 {%0,%1,%2,%3}, [%4];"
                 : "=r"(r0), "=r"(r1), "=r"(r2), "=r"(r3) : "r"(addr));
}
__device__ __forceinline__ void mma16816(float* c, const uint32_t* a, const uint32_t* b){
    asm volatile(
        "mma.sync.aligned.m16n8k16.row.col.f32.f16.f16.f32 "
        "{%0,%1,%2,%3}, {%4,%5,%6,%7}, {%8,%9}, {%0,%1,%2,%3};"
        : "+f"(c[0]), "+f"(c[1]), "+f"(c[2]), "+f"(c[3])
        : "r"(a[0]), "r"(a[1]), "r"(a[2]), "r"(a[3]), "r"(b[0]), "r"(b[1]));
}

// FMA-pipe 2^t (avoids MUFU bottleneck)
__device__ __forceinline__ float exp2p(float t){
    t = fmaxf(t, -100.f);
    float n = t + 12582912.f;
    n -= 12582912.f;
    float f = t - n;
    float fl = f * 0.6931471805599453f;
    float p = fmaf(fl, fmaf(fl, fmaf(fl, fmaf(fl, fmaf(fl, 0.0083333333f,
              0.0416666667f), 0.1666666667f), 0.5f), 1.f), 1.f);
    return __uint_as_float((uint32_t)((int)n + 127) << 23) * p;
}

// ---------------- x = a + b, emit fp32 + fp16 hi --------------------------------
__global__ __launch_bounds__(256) void add_convert(
    const float* __restrict__ a, const float* __restrict__ b,
    float* __restrict__ o, fp16* __restrict__ oh, int n4)
{
    int i = blockIdx.x * 256 + threadIdx.x;
    if (i >= n4) return;
    float4 av = ((const float4*)a)[i];
    float4 bv = ((const float4*)b)[i];
    float4 v;
    v.x = av.x + bv.x; v.y = av.y + bv.y; v.z = av.z + bv.z; v.w = av.w + bv.w;
    ((float4*)o)[i] = v;
    uint32_t h[2] = { pack_h2(v.x, v.y), pack_h2(v.z, v.w) };
    *(uint2*)(oh + (size_t)i * 4) = *(uint2*)h;
}

// ---------------- weight transpose + fp16 hi/lo split ---------------------------
__global__ __launch_bounds__(256) void wconvert_t(
    const float* __restrict__ W, fp16* __restrict__ Th, fp16* __restrict__ Tl,
    int K, int N)
{
    __shared__ float t[32][33];
    int n0 = blockIdx.x * 32, k0 = blockIdx.y * 32;
    int x = threadIdx.x, y = threadIdx.y;
    #pragma unroll
    for (int i = 0; i < 4; i++)
        t[y + 8*i][x] = W[(size_t)(k0 + y + 8*i) * N + n0 + x];
    __syncthreads();
    #pragma unroll
    for (int i = 0; i < 4; i++) {
        float v = t[x][y + 8*i];
        fp16 h, l; split2h(v, h, l);
        size_t idx = (size_t)(n0 + y + 8*i) * K + k0 + x;
        Th[idx] = h; Tl[idx] = l;
    }
}

__global__ void concat_bias(const float* __restrict__ a, const float* __restrict__ b,
                            const float* __restrict__ c, float* __restrict__ o)
{
    int i = blockIdx.x * 256 + threadIdx.x;
    if (i >= NQKV) return;
    o[i] = (i < 1024) ? a[i] : (i < 2048 ? b[i - 1024] : c[i - 2048]);
}

// ---------------- fp16x2 GEMM: C = Ah[M,K] @ (Bh+Bl)[N,K]^T + bias --------------
// CTA 128x256, 8 warps of 64x64, BK=64, cp.async double-buffer.
// stage: Ah @0 (16KB), Bh @16K (32KB), Bl @48K (32KB) = 80KB; 2 stages.
#define TBM 128
#define TBN 256
#define STAGE 81920
#define GEMM_SMEM (2*STAGE)

__global__ __launch_bounds__(256, 1) void gemm_tc(
    const uint4* __restrict__ Ah4,
    const uint4* __restrict__ Bh4, const uint4* __restrict__ Bl4,
    const float* __restrict__ bias,
    float* __restrict__ Cf, fp16* __restrict__ Ch, fp16* __restrict__ Cl,
    int M, int N, int K, int relu)
{
    extern __shared__ char smbuf[];
    const int tid = threadIdx.x;
    const int wid = tid >> 5;
    const int lane = tid & 31;
    const uint32_t sbase = smem_u32(smbuf);

    const int rowBase = blockIdx.y * TBM;
    const int colBase = blockIdx.x * TBN;
    const int K8 = K >> 3;
    const int nch = K >> 6;
    const int wm = (wid >> 2) * 64;
    const int wn = (wid & 3) * 64;

    auto issue_stage = [&](int chunk, int buf){
        uint32_t st = sbase + buf * STAGE;
        const int kc8 = chunk * 8;
        #pragma unroll
        for (int t = 0; t < 4; t++) {
            int id = tid + t * 256;
            int r = id >> 3, c = id & 7;
            cp16(st + SWZ(r * 128 + c * 16),
                 Ah4 + (size_t)(rowBase + r) * K8 + kc8 + c);
        }
        #pragma unroll
        for (int t = 0; t < 8; t++) {
            int id = tid + t * 256;
            int r = id >> 3, c = id & 7;
            uint32_t sw = SWZ(r * 128 + c * 16);
            size_t go = (size_t)(colBase + r) * K8 + kc8 + c;
            cp16(st + 16384 + sw, Bh4 + go);
            cp16(st + 49152 + sw, Bl4 + go);
        }
        cp_commit();
    };

    float acc[4][8][4];
    #pragma unroll
    for (int mt = 0; mt < 4; mt++)
        #pragma unroll
        for (int nt = 0; nt < 8; nt++)
            #pragma unroll
            for (int e = 0; e < 4; e++) acc[mt][nt][e] = 0.f;

    issue_stage(0, 0);
    issue_stage(1, 1);

    for (int i = 0; i < nch; i++) {
        cp_wait1();
        __syncthreads();
        const int buf = i & 1;
        const uint32_t ab = sbase + buf * STAGE;

        #pragma unroll
        for (int ks = 0; ks < 4; ks++) {
            const int kb = ks * 32;
            uint32_t af[4][4], bhf[4][4], blf[4][4];
            #pragma unroll
            for (int mt = 0; mt < 4; mt++) {
                uint32_t off = SWZ((wm + mt*16 + (lane & 15)) * 128 + kb + (lane >> 4) * 16);
                ldsm_x4(af[mt][0], af[mt][1], af[mt][2], af[mt][3], ab + off);
            }
            #pragma unroll
            for (int p = 0; p < 4; p++) {
                uint32_t off = SWZ((wn + p*16 + (lane & 15)) * 128 + kb + (lane >> 4) * 16);
                ldsm_x4(bhf[p][0], bhf[p][1], bhf[p][2], bhf[p][3], ab + 16384 + off);
                ldsm_x4(blf[p][0], blf[p][1], blf[p][2], blf[p][3], ab + 49152 + off);
            }
            #pragma unroll
            for (int mt = 0; mt < 4; mt++) {
                #pragma unroll
                for (int nt = 0; nt < 8; nt++) {
                    const int p = nt >> 1, q = nt & 1;
                    uint32_t bh2[2] = { bhf[p][q], bhf[p][q + 2] };
                    uint32_t bl2[2] = { blf[p][q], blf[p][q + 2] };
                    mma16816(acc[mt][nt], af[mt], bh2);
                    mma16816(acc[mt][nt], af[mt], bl2);
                }
            }
        }
        __syncthreads();
        if (i + 2 < nch) issue_stage(i + 2, buf);
        else cp_commit();
    }

    #pragma unroll
    for (int mt = 0; mt < 4; mt++) {
        #pragma unroll
        for (int nt = 0; nt < 8; nt++) {
            int r0 = rowBase + wm + mt*16 + (lane >> 2);
            int c0 = colBase + wn + nt*8 + (lane & 3) * 2;
            float2 bb = *(const float2*)(bias + c0);
            #pragma unroll
            for (int half = 0; half < 2; half++) {
                int r = r0 + half * 8;
                float vx = acc[mt][nt][half*2 + 0] + bb.x;
                float vy = acc[mt][nt][half*2 + 1] + bb.y;
                if (relu) { vx = fmaxf(vx, 0.f); vy = fmaxf(vy, 0.f); }
                if (Cf) {
                    float2 o2 = {vx, vy};
                    *(float2*)(Cf + (size_t)r * N + c0) = o2;
                }
                if (Ch) {
                    uint32_t hp = pack_h2(vx, vy);
                    *(uint32_t*)(Ch + (size_t)r * N + c0) = hp;
                    if (Cl) {
                        __half2 hh = *(__half2*)&hp;
                        uint32_t lp = pack_h2(vx - __half2float(hh.x),
                                              vy - __half2float(hh.y));
                        *(uint32_t*)(Cl + (size_t)r * N + c0) = lp;
                    }
                }
            }
        }
    }
}

// ---------------- tensor-core flash attention (fp16, 2-pass) --------------------
// Q/K/V from fused qkv buffer, pitch 3072 halfs (=384 uint4).
// smem: Qh 0, Kh 16K, Kl 32K, Vh 48K, Vl 64K (each 128x128B SW128) = 80KB
#define FA_SMEM 81920
#define QKV_P4 384
#define L2S 0.1803368801111f   // 0.125 * log2(e)

__global__ __launch_bounds__(256, 1) void flash_attn_tc(
    const uint4* __restrict__ qkvh, const uint4* __restrict__ qkvl,
    fp16* __restrict__ Oh)
{
    extern __shared__ char sm[];
    const uint32_t sb = smem_u32(sm);
    const int tid = threadIdx.x;
    const int wid = tid >> 5;
    const int lane = tid & 31;
    const int bh = blockIdx.y;
    const int b = bh >> 4, h = bh & 15;
    const int q0 = blockIdx.x * 128;

    // load Q hi
    #pragma unroll
    for (int t = 0; t < 4; t++) {
        int id = tid + t * 256;
        int r = id >> 3, c = id & 7;
        size_t src = (size_t)(b * Sq + q0 + r) * QKV_P4 + h * 8 + c;
        *(uint4*)(sm + SWZ(r * 128 + c * 16)) = qkvh[src];
    }
    __syncthreads();

    uint32_t qh[4][4];
    #pragma unroll
    for (int ks = 0; ks < 4; ks++) {
        uint32_t loc = SWZ((wid * 16 + (lane & 15)) * 128 + ks * 32 + (lane >> 4) * 16);
        ldsm_x4(qh[ks][0], qh[ks][1], qh[ks][2], qh[ks][3], sb + loc);
    }

    float o[8][4];
    #pragma unroll
    for (int u = 0; u < 8; u++)
        #pragma unroll
        for (int e = 0; e < 4; e++) o[u][e] = 0.f;
    float m0 = -1e30f, m1 = -1e30f, l0 = 0.f, l1 = 0.f;

    for (int j0 = 0; j0 < Sq; j0 += 128) {
        __syncthreads();
        #pragma unroll
        for (int t = 0; t < 4; t++) {
            int id = tid + t * 256;
            int r = id >> 3, c = id & 7;
            size_t srcK = (size_t)(b * Sq + j0 + r) * QKV_P4 + 128 + h * 8 + c;
            size_t srcV = (size_t)(b * Sq + j0 + r) * QKV_P4 + 256 + h * 8 + c;
            uint32_t sw = SWZ(r * 128 + c * 16);
            *(uint4*)(sm + 16384 + sw) = qkvh[srcK];
            *(uint4*)(sm + 32768 + sw) = qkvl[srcK];
            *(uint4*)(sm + 49152 + sw) = qkvh[srcV];
            *(uint4*)(sm + 65536 + sw) = qkvl[srcV];
        }
        __syncthreads();

        // S = QK^T (2-pass fp16)
        float s[16][4];
        #pragma unroll
        for (int t = 0; t < 16; t++)
            #pragma unroll
            for (int e = 0; e < 4; e++) s[t][e] = 0.f;

        #pragma unroll
        for (int nc = 0; nc < 8; nc++) {
            #pragma unroll
            for (int ks = 0; ks < 4; ks++) {
                uint32_t kh[4], kl[4];
                uint32_t loc = SWZ((nc * 16 + (lane & 15)) * 128 + ks * 32 + (lane >> 4) * 16);
                ldsm_x4(kh[0], kh[1], kh[2], kh[3], sb + 16384 + loc);
                ldsm_x4(kl[0], kl[1], kl[2], kl[3], sb + 32768 + loc);
                uint32_t bh0[2] = {kh[0], kh[2]}, bh1[2] = {kh[1], kh[3]};
                uint32_t bl0[2] = {kl[0], kl[2]}, bl1[2] = {kl[1], kl[3]};
                mma16816(s[2*nc],   qh[ks], bh0);
                mma16816(s[2*nc+1], qh[ks], bh1);
                mma16816(s[2*nc],   qh[ks], bl0);
                mma16816(s[2*nc+1], qh[ks], bl1);
            }
        }

        // online softmax
        float mx0 = -1e30f, mx1 = -1e30f;
        #pragma unroll
        for (int t = 0; t < 16; t++) {
            mx0 = fmaxf(mx0, fmaxf(s[t][0], s[t][1]));
            mx1 = fmaxf(mx1, fmaxf(s[t][2], s[t][3]));
        }
        mx0 = fmaxf(mx0, __shfl_xor_sync(0xffffffffu, mx0, 1));
        mx0 = fmaxf(mx0, __shfl_xor_sync(0xffffffffu, mx0, 2));
        mx1 = fmaxf(mx1, __shfl_xor_sync(0xffffffffu, mx1, 1));
        mx1 = fmaxf(mx1, __shfl_xor_sync(0xffffffffu, mx1, 2));
        float mn0 = fmaxf(m0, mx0), mn1 = fmaxf(m1, mx1);
        float c0 = exp2p((m0 - mn0) * L2S);
        float c1 = exp2p((m1 - mn1) * L2S);
        m0 = mn0; m1 = mn1;

        float sum0 = 0.f, sum1 = 0.f;
        uint32_t pA[16], pB[16];
        #pragma unroll
        for (int t = 0; t < 16; t++) {
            float p0 = exp2p((s[t][0] - mn0) * L2S);
            float p1 = exp2p((s[t][1] - mn0) * L2S);
            float p2 = exp2p((s[t][2] - mn1) * L2S);
            float p3 = exp2p((s[t][3] - mn1) * L2S);
            sum0 += p0 + p1;
            sum1 += p2 + p3;
            pA[t] = pack_h2(p0, p1);
            pB[t] = pack_h2(p2, p3);
        }
        sum0 += __shfl_xor_sync(0xffffffffu, sum0, 1);
        sum0 += __shfl_xor_sync(0xffffffffu, sum0, 2);
        sum1 += __shfl_xor_sync(0xffffffffu, sum1, 1);
        sum1 += __shfl_xor_sync(0xffffffffu, sum1, 2);
        l0 = l0 * c0 + sum0;
        l1 = l1 * c1 + sum1;
        #pragma unroll
        for (int u = 0; u < 8; u++) {
            o[u][0] *= c0; o[u][1] *= c0;
            o[u][2] *= c1; o[u][3] *= c1;
        }

        // O += P @ V (2-pass fp16: Ph*Vh + Ph*Vl)
        #pragma unroll
        for (int j = 0; j < 8; j++) {
            uint32_t ah[4] = {pA[2*j], pB[2*j], pA[2*j+1], pB[2*j+1]};
            #pragma unroll
            for (int p = 0; p < 4; p++) {
                uint32_t vh[4], vl[4];
                uint32_t loc = SWZ((j * 16 + (lane & 15)) * 128 + p * 32 + (lane >> 4) * 16);
                ldsm_x4_t(vh[0], vh[1], vh[2], vh[3], sb + 49152 + loc);
                ldsm_x4_t(vl[0], vl[1], vl[2], vl[3], sb + 65536 + loc);
                uint32_t bh0[2] = {vh[0], vh[1]}, bh1[2] = {vh[2], vh[3]};
                uint32_t bl0[2] = {vl[0], vl[1]}, bl1[2] = {vl[2], vl[3]};
                mma16816(o[2*p],   ah, bh0);
                mma16816(o[2*p+1], ah, bh1);
                mma16816(o[2*p],   ah, bl0);
                mma16816(o[2*p+1], ah, bl1);
            }
        }
    }

    float inv0 = 1.f / l0, inv1 = 1.f / l1;
    int r0 = q0 + wid * 16 + (lane >> 2);
    int r1 = r0 + 8;
    #pragma unroll
    for (int u = 0; u < 8; u++) {
        int col = h * 64 + u * 8 + (lane & 3) * 2;
        *(uint32_t*)(Oh + (size_t)(b * Sq + r0) * Dm + col) =
            pack_h2(o[u][0] * inv0, o[u][1] * inv0);
        *(uint32_t*)(Oh + (size_t)(b * Sq + r1) * Dm + col) =
            pack_h2(o[u][2] * inv1, o[u][3] * inv1);
    }
}

// ---------------- LayerNorm + residual -------------------------------------------
__global__ __launch_bounds__(256) void ln_residual_kernel(
    const float* __restrict__ res, const float* __restrict__ x,
    const float* __restrict__ g, const float* __restrict__ be,
    float* __restrict__ out, fp16* __restrict__ oh)
{
    const int row = blockIdx.x;
    const int tid = threadIdx.x;
    const float* xr = x + (size_t)row * Dm;

    float4 v = *(const float4*)(xr + tid * 4);
    float s1 = v.x + v.y + v.z + v.w;
    float s2 = v.x * v.x + v.y * v.y + v.z * v.z + v.w * v.w;
    #pragma unroll
    for (int off = 16; off; off >>= 1) {
        s1 += __shfl_xor_sync(0xffffffffu, s1, off);
        s2 += __shfl_xor_sync(0xffffffffu, s2, off);
    }
    __shared__ float r1[8], r2[8];
    if ((tid & 31) == 0) { r1[tid >> 5] = s1; r2[tid >> 5] = s2; }
    __syncthreads();
    float t1 = 0.f, t2 = 0.f;
    #pragma unroll
    for (int w = 0; w < 8; w++) { t1 += r1[w]; t2 += r2[w]; }

    const float mu  = t1 * (1.f / Dm);
    const float var = t2 * (1.f / Dm) - mu * mu;
    const float rstd = rsqrtf(var + 1e-6f);

    float4 rv = *(const float4*)(res + (size_t)row * Dm + tid * 4);
    float4 gv = *(const float4*)(g + tid * 4);
    float4 bv = *(const float4*)(be + tid * 4);
    float4 ov;
    ov.x = rv.x + (v.x - mu) * rstd * gv.x + bv.x;
    ov.y = rv.y + (v.y - mu) * rstd * gv.y + bv.y;
    ov.z = rv.z + (v.z - mu) * rstd * gv.z + bv.z;
    ov.w = rv.w + (v.w - mu) * rstd * gv.w + bv.w;
    *(float4*)(out + (size_t)row * Dm + tid * 4) = ov;
    if (oh) {
        uint32_t h2[2] = { pack_h2(ov.x, ov.y), pack_h2(ov.z, ov.w) };
        *(uint2*)(oh + (size_t)row * Dm + tid * 4) = *(uint2*)h2;
    }
}

// ---------------- launch ----------------------------------------------------------
extern "C" void kernel_launch(void* const* d_in, const int* in_sizes, int n_in,
                              void* d_out, int out_size)
{
    const float* x_enc = (const float*)d_in[0];
    const float* x_pos = (const float*)d_in[1];
    const float* wq = (const float*)d_in[2];  const float* bq = (const float*)d_in[3];
    const float* wk = (const float*)d_in[4];  const float* bk = (const float*)d_in[5];
    const float* wv = (const float*)d_in[6];  const float* bv = (const float*)d_in[7];
    const float* wc = (const float*)d_in[8];  const float* bc = (const float*)d_in[9];
    const float* w1 = (const float*)d_in[10]; const float* b1 = (const float*)d_in[11];
    const float* w2 = (const float*)d_in[12]; const float* b2 = (const float*)d_in[13];
    const float* g1 = (const float*)d_in[14]; const float* be1 = (const float*)d_in[15];
    const float* g2 = (const float*)d_in[16]; const float* be2 = (const float*)d_in[17];
    float* out = (float*)d_out;

    float *gx, *gproj, *ga, *gffn, *gbqkv;
    fp16 *gxh, *gath, *gah, *gh1h;
    fp16 *wqkvh, *wqkvl, *wch, *wcl, *w1h, *w1l, *w2h, *w2l, *gqkvh, *gqkvl;
    cudaGetSymbolAddress((void**)&gx,    g_x);
    cudaGetSymbolAddress((void**)&gxh,   g_xh);
    cudaGetSymbolAddress((void**)&wqkvh, g_wqkvh); cudaGetSymbolAddress((void**)&wqkvl, g_wqkvl);
    cudaGetSymbolAddress((void**)&wch,   g_wch);   cudaGetSymbolAddress((void**)&wcl,   g_wcl);
    cudaGetSymbolAddress((void**)&w1h,   g_w1h);   cudaGetSymbolAddress((void**)&w1l,   g_w1l);
    cudaGetSymbolAddress((void**)&w2h,   g_w2h);   cudaGetSymbolAddress((void**)&w2l,   g_w2l);
    cudaGetSymbolAddress((void**)&gbqkv, g_bqkv);
    cudaGetSymbolAddress((void**)&gqkvh, g_qkvh);  cudaGetSymbolAddress((void**)&gqkvl, g_qkvl);
    cudaGetSymbolAddress((void**)&gath,  g_ath);
    cudaGetSymbolAddress((void**)&gproj, g_proj);
    cudaGetSymbolAddress((void**)&ga,    g_a);
    cudaGetSymbolAddress((void**)&gah,   g_ah);
    cudaGetSymbolAddress((void**)&gh1h,  g_h1h);
    cudaGetSymbolAddress((void**)&gffn,  g_ffn);

    cudaFuncSetAttribute(gemm_tc, cudaFuncAttributeMaxDynamicSharedMemorySize, GEMM_SMEM);
    cudaFuncSetAttribute(flash_attn_tc, cudaFuncAttributeMaxDynamicSharedMemorySize, FA_SMEM);

    auto launch_gemm = [&](const fp16* Ah, const fp16* Bh, const fp16* Bl,
                           const float* bias, float* Cf, fp16* Ch, fp16* Cl,
                           int M, int N, int K, int relu) {
        dim3 grid(N / TBN, M / TBM);
        gemm_tc<<<grid, 256, GEMM_SMEM>>>(
            (const uint4*)Ah, (const uint4*)Bh, (const uint4*)Bl,
            bias, Cf, Ch, Cl, M, N, K, relu);
    };

    dim3 tb(32, 8);
    const int n4 = NTOK * Dm / 4;

    // 1: x = x_enc + x_pos
    add_convert<<<n4 / 256, 256>>>(x_enc, x_pos, gx, gxh, n4);
    // 2-4: QKV weights into fused buffer
    wconvert_t<<<dim3(Dm/32, Dm/32), tb>>>(wq, wqkvh,                      wqkvl,                      Dm, Dm);
    wconvert_t<<<dim3(Dm/32, Dm/32), tb>>>(wk, wqkvh + (size_t)Dm*Dm,      wqkvl + (size_t)Dm*Dm,      Dm, Dm);
    wconvert_t<<<dim3(Dm/32, Dm/32), tb>>>(wv, wqkvh + (size_t)2*Dm*Dm,    wqkvl + (size_t)2*Dm*Dm,    Dm, Dm);
    // 5: fused bias
    concat_bias<<<(NQKV + 255) / 256, 256>>>(bq, bk, bv, gbqkv);
    // 6: fused QKV GEMM  (ncu -s 5 -c 1 profiles this one)
    launch_gemm(gxh, wqkvh, wqkvl, gbqkv, nullptr, gqkvh, gqkvl, NTOK, NQKV, Dm, 0);
    // 7: flash attention
    flash_attn_tc<<<dim3(Sq / 128, Bsz * Hh), 256, FA_SMEM>>>(
        (const uint4*)gqkvh, (const uint4*)gqkvl, gath);
    // 8: wc convert, 9: output projection
    wconvert_t<<<dim3(Dm/32, Dm/32), tb>>>(wc, wch, wcl, Dm, Dm);
    launch_gemm(gath, wch, wcl, bc, gproj, nullptr, nullptr, NTOK, Dm, Dm, 0);
    // 10: a = x + LN(proj)
    ln_residual_kernel<<<NTOK, 256>>>(gx, gproj, g1, be1, ga, gah);
    // 11-12: FFN weights
    wconvert_t<<<dim3(Ff/32, Dm/32), tb>>>(w1, w1h, w1l, Dm, Ff);
    wconvert_t<<<dim3(Dm/32, Ff/32), tb>>>(w2, w2h, w2l, Ff, Dm);
    // 13-14: FFN
    launch_gemm(gah, w1h, w1l, b1, nullptr, gh1h, nullptr, NTOK, Ff, Dm, 1);
    launch_gemm(gh1h, w2h, w2l, b2, gffn, nullptr, nullptr, NTOK, Dm, Ff, 0);
    // 15: out = a + LN(ffn)
    ln_residual_kernel<<<NTOK, 256>>>(ga, gffn, g2, be2, out, nullptr);
}

// round 6
// speedup vs baseline: 3.6402x; 1.0566x over previous
#include <cuda_runtime.h>
#include <cuda_fp16.h>
#include <cstdint>
#include <math.h>

#define Bsz 2
#define Sq 2048
#define Dm 1024
#define Hh 16
#define DHd 64
#define Ff 4096
#define NTOK (Bsz*Sq)
#define NQKV 3072

typedef __half fp16;

// ---------------- scratch (device globals) ------------------------------------
__device__ float g_x[(size_t)NTOK*Dm];
__device__ fp16  g_xh[(size_t)NTOK*Dm];

__device__ fp16 g_wqkvh[(size_t)NQKV*Dm], g_wqkvl[(size_t)NQKV*Dm]; // [N=3K,K=D]
__device__ fp16 g_wch[(size_t)Dm*Dm], g_wcl[(size_t)Dm*Dm];
__device__ fp16 g_w1h[(size_t)Ff*Dm], g_w1l[(size_t)Ff*Dm];
__device__ fp16 g_w2h[(size_t)Dm*Ff], g_w2l[(size_t)Dm*Ff];
__device__ float g_bqkv[NQKV];

__device__ fp16 g_qkvh[(size_t)NTOK*NQKV], g_qkvl[(size_t)NTOK*NQKV];
__device__ fp16 g_ath[(size_t)NTOK*Dm];
__device__ float g_proj[(size_t)NTOK*Dm];
__device__ float g_a[(size_t)NTOK*Dm];
__device__ fp16  g_ah[(size_t)NTOK*Dm];
__device__ fp16  g_h1h[(size_t)NTOK*Ff];
__device__ float g_ffn[(size_t)NTOK*Dm];

// ---------------- helpers -------------------------------------------------------
__device__ __forceinline__ uint32_t smem_u32(const void* p){
    uint32_t a;
    asm("{ .reg .u64 t; cvta.to.shared.u64 t, %1; cvt.u32.u64 %0, t; }" : "=r"(a) : "l"(p));
    return a;
}
#define SWZ(x) ((x) ^ (((x) >> 3) & 0x70))

__device__ __forceinline__ void split2h(float v, fp16& h, fp16& l){
    h = __float2half_rn(v);
    l = __float2half_rn(v - __half2float(h));
}
__device__ __forceinline__ uint32_t pack_h2(float a, float b){
    __half2 t = __floats2half2_rn(a, b);
    return *(uint32_t*)&t;
}
__device__ __forceinline__ void cp16(uint32_t dst, const void* src){
    asm volatile("cp.async.cg.shared.global [%0], [%1], 16;" :: "r"(dst), "l"(src));
}
__device__ __forceinline__ void cp_commit(){
    asm volatile("cp.async.commit_group;" ::: "memory");
}
__device__ __forceinline__ void cp_wait1(){
    asm volatile("cp.async.wait_group 1;" ::: "memory");
}

__device__ __forceinline__ void ldsm_x4(uint32_t& r0, uint32_t& r1, uint32_t& r2,
                                        uint32_t& r3, uint32_t addr){
    asm volatile("ldmatrix.sync.aligned.m8n8.x4.shared.b16 {%0,%1,%2,%3}, [%4];"
                 : "=r"(r0), "=r"(r1), "=r"(r2), "=r"(r3) : "r"(addr));
}
__device__ __forceinline__ void ldsm_x4_t(uint32_t& r0, uint32_t& r1, uint32_t& r2,
                                          uint32_t& r3, uint32_t addr){
    asm volatile("ldmatrix.sync.aligned.m8n8.x4.trans.shared.b16 {%0,%1,%2,%3}, [%4];"
                 : "=r"(r0), "=r"(r1), "=r"(r2), "=r"(r3) : "r"(addr));
}
__device__ __forceinline__ void mma16816(float* c, const uint32_t* a, const uint32_t* b){
    asm volatile(
        "mma.sync.aligned.m16n8k16.row.col.f32.f16.f16.f32 "
        "{%0,%1,%2,%3}, {%4,%5,%6,%7}, {%8,%9}, {%0,%1,%2,%3};"
        : "+f"(c[0]), "+f"(c[1]), "+f"(c[2]), "+f"(c[3])
        : "r"(a[0]), "r"(a[1]), "r"(a[2]), "r"(a[3]), "r"(b[0]), "r"(b[1]));
}

// FMA-pipe 2^t (avoids MUFU bottleneck)
__device__ __forceinline__ float exp2p(float t){
    t = fmaxf(t, -100.f);
    float n = t + 12582912.f;
    n -= 12582912.f;
    float f = t - n;
    float fl = f * 0.6931471805599453f;
    float p = fmaf(fl, fmaf(fl, fmaf(fl, fmaf(fl, fmaf(fl, 0.0083333333f,
              0.0416666667f), 0.1666666667f), 0.5f), 1.f), 1.f);
    return __uint_as_float((uint32_t)((int)n + 127) << 23) * p;
}

// ---------------- x = a + b, emit fp32 + fp16 hi --------------------------------
__global__ __launch_bounds__(256) void add_convert(
    const float* __restrict__ a, const float* __restrict__ b,
    float* __restrict__ o, fp16* __restrict__ oh, int n4)
{
    int i = blockIdx.x * 256 + threadIdx.x;
    if (i >= n4) return;
    float4 av = ((const float4*)a)[i];
    float4 bv = ((const float4*)b)[i];
    float4 v;
    v.x = av.x + bv.x; v.y = av.y + bv.y; v.z = av.z + bv.z; v.w = av.w + bv.w;
    ((float4*)o)[i] = v;
    uint32_t h[2] = { pack_h2(v.x, v.y), pack_h2(v.z, v.w) };
    *(uint2*)(oh + (size_t)i * 4) = *(uint2*)h;
}

// ---------------- weight transpose + fp16 hi/lo split ---------------------------
__global__ __launch_bounds__(256) void wconvert_t(
    const float* __restrict__ W, fp16* __restrict__ Th, fp16* __restrict__ Tl,
    int K, int N)
{
    __shared__ float t[32][33];
    int n0 = blockIdx.x * 32, k0 = blockIdx.y * 32;
    int x = threadIdx.x, y = threadIdx.y;
    #pragma unroll
    for (int i = 0; i < 4; i++)
        t[y + 8*i][x] = W[(size_t)(k0 + y + 8*i) * N + n0 + x];
    __syncthreads();
    #pragma unroll
    for (int i = 0; i < 4; i++) {
        float v = t[x][y + 8*i];
        fp16 h, l; split2h(v, h, l);
        size_t idx = (size_t)(n0 + y + 8*i) * K + k0 + x;
        Th[idx] = h; Tl[idx] = l;
    }
}

__global__ void concat_bias(const float* __restrict__ a, const float* __restrict__ b,
                            const float* __restrict__ c, float* __restrict__ o)
{
    int i = blockIdx.x * 256 + threadIdx.x;
    if (i >= NQKV) return;
    o[i] = (i < 1024) ? a[i] : (i < 2048 ? b[i - 1024] : c[i - 2048]);
}

// ---------------- fp16x2 GEMM: C = Ah[M,K] @ (Bh+Bl)[N,K]^T + bias --------------
#define TBM 128
#define TBN 256
#define STAGE 81920
#define GEMM_SMEM (2*STAGE)

__global__ __launch_bounds__(256, 1) void gemm_tc(
    const uint4* __restrict__ Ah4,
    const uint4* __restrict__ Bh4, const uint4* __restrict__ Bl4,
    const float* __restrict__ bias,
    float* __restrict__ Cf, fp16* __restrict__ Ch, fp16* __restrict__ Cl,
    int M, int N, int K, int relu)
{
    extern __shared__ char smbuf[];
    const int tid = threadIdx.x;
    const int wid = tid >> 5;
    const int lane = tid & 31;
    const uint32_t sbase = smem_u32(smbuf);

    const int rowBase = blockIdx.y * TBM;
    const int colBase = blockIdx.x * TBN;
    const int K8 = K >> 3;
    const int nch = K >> 6;
    const int wm = (wid >> 2) * 64;
    const int wn = (wid & 3) * 64;

    auto issue_stage = [&](int chunk, int buf){
        uint32_t st = sbase + buf * STAGE;
        const int kc8 = chunk * 8;
        #pragma unroll
        for (int t = 0; t < 4; t++) {
            int id = tid + t * 256;
            int r = id >> 3, c = id & 7;
            cp16(st + SWZ(r * 128 + c * 16),
                 Ah4 + (size_t)(rowBase + r) * K8 + kc8 + c);
        }
        #pragma unroll
        for (int t = 0; t < 8; t++) {
            int id = tid + t * 256;
            int r = id >> 3, c = id & 7;
            uint32_t sw = SWZ(r * 128 + c * 16);
            size_t go = (size_t)(colBase + r) * K8 + kc8 + c;
            cp16(st + 16384 + sw, Bh4 + go);
            cp16(st + 49152 + sw, Bl4 + go);
        }
        cp_commit();
    };

    float acc[4][8][4];
    #pragma unroll
    for (int mt = 0; mt < 4; mt++)
        #pragma unroll
        for (int nt = 0; nt < 8; nt++)
            #pragma unroll
            for (int e = 0; e < 4; e++) acc[mt][nt][e] = 0.f;

    issue_stage(0, 0);
    issue_stage(1, 1);

    for (int i = 0; i < nch; i++) {
        cp_wait1();
        __syncthreads();
        const int buf = i & 1;
        const uint32_t ab = sbase + buf * STAGE;

        #pragma unroll
        for (int ks = 0; ks < 4; ks++) {
            const int kb = ks * 32;
            uint32_t af[4][4], bhf[4][4], blf[4][4];
            #pragma unroll
            for (int mt = 0; mt < 4; mt++) {
                uint32_t off = SWZ((wm + mt*16 + (lane & 15)) * 128 + kb + (lane >> 4) * 16);
                ldsm_x4(af[mt][0], af[mt][1], af[mt][2], af[mt][3], ab + off);
            }
            #pragma unroll
            for (int p = 0; p < 4; p++) {
                uint32_t off = SWZ((wn + p*16 + (lane & 15)) * 128 + kb + (lane >> 4) * 16);
                ldsm_x4(bhf[p][0], bhf[p][1], bhf[p][2], bhf[p][3], ab + 16384 + off);
                ldsm_x4(blf[p][0], blf[p][1], blf[p][2], blf[p][3], ab + 49152 + off);
            }
            #pragma unroll
            for (int mt = 0; mt < 4; mt++) {
                #pragma unroll
                for (int nt = 0; nt < 8; nt++) {
                    const int p = nt >> 1, q = nt & 1;
                    uint32_t bh2[2] = { bhf[p][q], bhf[p][q + 2] };
                    uint32_t bl2[2] = { blf[p][q], blf[p][q + 2] };
                    mma16816(acc[mt][nt], af[mt], bh2);
                    mma16816(acc[mt][nt], af[mt], bl2);
                }
            }
        }
        __syncthreads();
        if (i + 2 < nch) issue_stage(i + 2, buf);
        else cp_commit();
    }

    #pragma unroll
    for (int mt = 0; mt < 4; mt++) {
        #pragma unroll
        for (int nt = 0; nt < 8; nt++) {
            int r0 = rowBase + wm + mt*16 + (lane >> 2);
            int c0 = colBase + wn + nt*8 + (lane & 3) * 2;
            float2 bb = *(const float2*)(bias + c0);
            #pragma unroll
            for (int half = 0; half < 2; half++) {
                int r = r0 + half * 8;
                float vx = acc[mt][nt][half*2 + 0] + bb.x;
                float vy = acc[mt][nt][half*2 + 1] + bb.y;
                if (relu) { vx = fmaxf(vx, 0.f); vy = fmaxf(vy, 0.f); }
                if (Cf) {
                    float2 o2 = {vx, vy};
                    *(float2*)(Cf + (size_t)r * N + c0) = o2;
                }
                if (Ch) {
                    uint32_t hp = pack_h2(vx, vy);
                    *(uint32_t*)(Ch + (size_t)r * N + c0) = hp;
                    if (Cl) {
                        __half2 hh = *(__half2*)&hp;
                        uint32_t lp = pack_h2(vx - __half2float(hh.x),
                                              vy - __half2float(hh.y));
                        *(uint32_t*)(Cl + (size_t)r * N + c0) = lp;
                    }
                }
            }
        }
    }
}

// ---------------- tensor-core flash attention (fp16 2-pass, cp.async dbl-buf) ---
// smem: Qh @0 (16K); stage s: Kh,Kl,Vh,Vl (16K each) @ 16K + s*64K. Total 144K.
#define FA_STAGE 65536
#define FA_SMEM (16384 + 2*FA_STAGE)
#define QKV_P4 384
#define L2S 0.1803368801111f   // 0.125 * log2(e)

__global__ __launch_bounds__(256, 1) void flash_attn_tc(
    const uint4* __restrict__ qkvh, const uint4* __restrict__ qkvl,
    fp16* __restrict__ Oh)
{
    extern __shared__ char sm[];
    const uint32_t sb = smem_u32(sm);
    const int tid = threadIdx.x;
    const int wid = tid >> 5;
    const int lane = tid & 31;
    const int bh = blockIdx.y;
    const int b = bh >> 4, h = bh & 15;
    const int q0 = blockIdx.x * 128;

    // async KV stage loader: Kh, Kl, Vh, Vl tiles for kv rows [j0, j0+128)
    auto issue_kv = [&](int j0, int buf){
        uint32_t st = sb + 16384 + buf * FA_STAGE;
        #pragma unroll
        for (int t = 0; t < 4; t++) {
            int id = tid + t * 256;
            int r = id >> 3, c = id & 7;
            size_t rowOff = (size_t)(b * Sq + j0 + r) * QKV_P4 + h * 8 + c;
            uint32_t sw = SWZ(r * 128 + c * 16);
            cp16(st +         sw, qkvh + rowOff + 128);  // Kh
            cp16(st + 16384 + sw, qkvl + rowOff + 128);  // Kl
            cp16(st + 32768 + sw, qkvh + rowOff + 256);  // Vh
            cp16(st + 49152 + sw, qkvl + rowOff + 256);  // Vl
        }
        cp_commit();
    };

    // load Q hi (sync; once)
    #pragma unroll
    for (int t = 0; t < 4; t++) {
        int id = tid + t * 256;
        int r = id >> 3, c = id & 7;
        size_t src = (size_t)(b * Sq + q0 + r) * QKV_P4 + h * 8 + c;
        *(uint4*)(sm + SWZ(r * 128 + c * 16)) = qkvh[src];
    }
    issue_kv(0, 0);
    issue_kv(128, 1);
    __syncthreads();

    uint32_t qh[4][4];
    #pragma unroll
    for (int ks = 0; ks < 4; ks++) {
        uint32_t loc = SWZ((wid * 16 + (lane & 15)) * 128 + ks * 32 + (lane >> 4) * 16);
        ldsm_x4(qh[ks][0], qh[ks][1], qh[ks][2], qh[ks][3], sb + loc);
    }

    float o[8][4];
    #pragma unroll
    for (int u = 0; u < 8; u++)
        #pragma unroll
        for (int e = 0; e < 4; e++) o[u][e] = 0.f;
    float m0 = -1e30f, m1 = -1e30f, l0 = 0.f, l1 = 0.f;

    for (int j0 = 0; j0 < Sq; j0 += 128) {
        cp_wait1();
        __syncthreads();
        const int buf = (j0 >> 7) & 1;
        const uint32_t kb = sb + 16384 + buf * FA_STAGE;

        // S = QK^T (2-pass fp16)
        float s[16][4];
        #pragma unroll
        for (int t = 0; t < 16; t++)
            #pragma unroll
            for (int e = 0; e < 4; e++) s[t][e] = 0.f;

        #pragma unroll
        for (int nc = 0; nc < 8; nc++) {
            #pragma unroll
            for (int ks = 0; ks < 4; ks++) {
                uint32_t kh[4], kl[4];
                uint32_t loc = SWZ((nc * 16 + (lane & 15)) * 128 + ks * 32 + (lane >> 4) * 16);
                ldsm_x4(kh[0], kh[1], kh[2], kh[3], kb + loc);
                ldsm_x4(kl[0], kl[1], kl[2], kl[3], kb + 16384 + loc);
                uint32_t bh0[2] = {kh[0], kh[2]}, bh1[2] = {kh[1], kh[3]};
                uint32_t bl0[2] = {kl[0], kl[2]}, bl1[2] = {kl[1], kl[3]};
                mma16816(s[2*nc],   qh[ks], bh0);
                mma16816(s[2*nc+1], qh[ks], bh1);
                mma16816(s[2*nc],   qh[ks], bl0);
                mma16816(s[2*nc+1], qh[ks], bl1);
            }
        }

        // online softmax
        float mx0 = -1e30f, mx1 = -1e30f;
        #pragma unroll
        for (int t = 0; t < 16; t++) {
            mx0 = fmaxf(mx0, fmaxf(s[t][0], s[t][1]));
            mx1 = fmaxf(mx1, fmaxf(s[t][2], s[t][3]));
        }
        mx0 = fmaxf(mx0, __shfl_xor_sync(0xffffffffu, mx0, 1));
        mx0 = fmaxf(mx0, __shfl_xor_sync(0xffffffffu, mx0, 2));
        mx1 = fmaxf(mx1, __shfl_xor_sync(0xffffffffu, mx1, 1));
        mx1 = fmaxf(mx1, __shfl_xor_sync(0xffffffffu, mx1, 2));
        float mn0 = fmaxf(m0, mx0), mn1 = fmaxf(m1, mx1);
        float c0 = exp2p((m0 - mn0) * L2S);
        float c1 = exp2p((m1 - mn1) * L2S);
        m0 = mn0; m1 = mn1;

        float sum0 = 0.f, sum1 = 0.f;
        uint32_t pA[16], pB[16];
        #pragma unroll
        for (int t = 0; t < 16; t++) {
            float p0 = exp2p((s[t][0] - mn0) * L2S);
            float p1 = exp2p((s[t][1] - mn0) * L2S);
            float p2 = exp2p((s[t][2] - mn1) * L2S);
            float p3 = exp2p((s[t][3] - mn1) * L2S);
            sum0 += p0 + p1;
            sum1 += p2 + p3;
            pA[t] = pack_h2(p0, p1);
            pB[t] = pack_h2(p2, p3);
        }
        sum0 += __shfl_xor_sync(0xffffffffu, sum0, 1);
        sum0 += __shfl_xor_sync(0xffffffffu, sum0, 2);
        sum1 += __shfl_xor_sync(0xffffffffu, sum1, 1);
        sum1 += __shfl_xor_sync(0xffffffffu, sum1, 2);
        l0 = l0 * c0 + sum0;
        l1 = l1 * c1 + sum1;
        #pragma unroll
        for (int u = 0; u < 8; u++) {
            o[u][0] *= c0; o[u][1] *= c0;
            o[u][2] *= c1; o[u][3] *= c1;
        }

        // O += P @ V (2-pass fp16: Ph*Vh + Ph*Vl)
        #pragma unroll
        for (int j = 0; j < 8; j++) {
            uint32_t ah[4] = {pA[2*j], pB[2*j], pA[2*j+1], pB[2*j+1]};
            #pragma unroll
            for (int p = 0; p < 4; p++) {
                uint32_t vh[4], vl[4];
                uint32_t loc = SWZ((j * 16 + (lane & 15)) * 128 + p * 32 + (lane >> 4) * 16);
                ldsm_x4_t(vh[0], vh[1], vh[2], vh[3], kb + 32768 + loc);
                ldsm_x4_t(vl[0], vl[1], vl[2], vl[3], kb + 49152 + loc);
                uint32_t bh0[2] = {vh[0], vh[1]}, bh1[2] = {vh[2], vh[3]};
                uint32_t bl0[2] = {vl[0], vl[1]}, bl1[2] = {vl[2], vl[3]};
                mma16816(o[2*p],   ah, bh0);
                mma16816(o[2*p+1], ah, bh1);
                mma16816(o[2*p],   ah, bl0);
                mma16816(o[2*p+1], ah, bl1);
            }
        }

        __syncthreads();  // all warps done reading this stage
        if (j0 + 256 < Sq) issue_kv(j0 + 256, buf);
        else cp_commit();   // keep group accounting uniform
    }

    float inv0 = 1.f / l0, inv1 = 1.f / l1;
    int r0 = q0 + wid * 16 + (lane >> 2);
    int r1 = r0 + 8;
    #pragma unroll
    for (int u = 0; u < 8; u++) {
        int col = h * 64 + u * 8 + (lane & 3) * 2;
        *(uint32_t*)(Oh + (size_t)(b * Sq + r0) * Dm + col) =
            pack_h2(o[u][0] * inv0, o[u][1] * inv0);
        *(uint32_t*)(Oh + (size_t)(b * Sq + r1) * Dm + col) =
            pack_h2(o[u][2] * inv1, o[u][3] * inv1);
    }
}

// ---------------- LayerNorm + residual -------------------------------------------
__global__ __launch_bounds__(256) void ln_residual_kernel(
    const float* __restrict__ res, const float* __restrict__ x,
    const float* __restrict__ g, const float* __restrict__ be,
    float* __restrict__ out, fp16* __restrict__ oh)
{
    const int row = blockIdx.x;
    const int tid = threadIdx.x;
    const float* xr = x + (size_t)row * Dm;

    float4 v = *(const float4*)(xr + tid * 4);
    float s1 = v.x + v.y + v.z + v.w;
    float s2 = v.x * v.x + v.y * v.y + v.z * v.z + v.w * v.w;
    #pragma unroll
    for (int off = 16; off; off >>= 1) {
        s1 += __shfl_xor_sync(0xffffffffu, s1, off);
        s2 += __shfl_xor_sync(0xffffffffu, s2, off);
    }
    __shared__ float r1[8], r2[8];
    if ((tid & 31) == 0) { r1[tid >> 5] = s1; r2[tid >> 5] = s2; }
    __syncthreads();
    float t1 = 0.f, t2 = 0.f;
    #pragma unroll
    for (int w = 0; w < 8; w++) { t1 += r1[w]; t2 += r2[w]; }

    const float mu  = t1 * (1.f / Dm);
    const float var = t2 * (1.f / Dm) - mu * mu;
    const float rstd = rsqrtf(var + 1e-6f);

    float4 rv = *(const float4*)(res + (size_t)row * Dm + tid * 4);
    float4 gv = *(const float4*)(g + tid * 4);
    float4 bv = *(const float4*)(be + tid * 4);
    float4 ov;
    ov.x = rv.x + (v.x - mu) * rstd * gv.x + bv.x;
    ov.y = rv.y + (v.y - mu) * rstd * gv.y + bv.y;
    ov.z = rv.z + (v.z - mu) * rstd * gv.z + bv.z;
    ov.w = rv.w + (v.w - mu) * rstd * gv.w + bv.w;
    *(float4*)(out + (size_t)row * Dm + tid * 4) = ov;
    if (oh) {
        uint32_t h2[2] = { pack_h2(ov.x, ov.y), pack_h2(ov.z, ov.w) };
        *(uint2*)(oh + (size_t)row * Dm + tid * 4) = *(uint2*)h2;
    }
}

// ---------------- launch ----------------------------------------------------------
extern "C" void kernel_launch(void* const* d_in, const int* in_sizes, int n_in,
                              void* d_out, int out_size)
{
    const float* x_enc = (const float*)d_in[0];
    const float* x_pos = (const float*)d_in[1];
    const float* wq = (const float*)d_in[2];  const float* bq = (const float*)d_in[3];
    const float* wk = (const float*)d_in[4];  const float* bk = (const float*)d_in[5];
    const float* wv = (const float*)d_in[6];  const float* bv = (const float*)d_in[7];
    const float* wc = (const float*)d_in[8];  const float* bc = (const float*)d_in[9];
    const float* w1 = (const float*)d_in[10]; const float* b1 = (const float*)d_in[11];
    const float* w2 = (const float*)d_in[12]; const float* b2 = (const float*)d_in[13];
    const float* g1 = (const float*)d_in[14]; const float* be1 = (const float*)d_in[15];
    const float* g2 = (const float*)d_in[16]; const float* be2 = (const float*)d_in[17];
    float* out = (float*)d_out;

    float *gx, *gproj, *ga, *gffn, *gbqkv;
    fp16 *gxh, *gath, *gah, *gh1h;
    fp16 *wqkvh, *wqkvl, *wch, *wcl, *w1h, *w1l, *w2h, *w2l, *gqkvh, *gqkvl;
    cudaGetSymbolAddress((void**)&gx,    g_x);
    cudaGetSymbolAddress((void**)&gxh,   g_xh);
    cudaGetSymbolAddress((void**)&wqkvh, g_wqkvh); cudaGetSymbolAddress((void**)&wqkvl, g_wqkvl);
    cudaGetSymbolAddress((void**)&wch,   g_wch);   cudaGetSymbolAddress((void**)&wcl,   g_wcl);
    cudaGetSymbolAddress((void**)&w1h,   g_w1h);   cudaGetSymbolAddress((void**)&w1l,   g_w1l);
    cudaGetSymbolAddress((void**)&w2h,   g_w2h);   cudaGetSymbolAddress((void**)&w2l,   g_w2l);
    cudaGetSymbolAddress((void**)&gbqkv, g_bqkv);
    cudaGetSymbolAddress((void**)&gqkvh, g_qkvh);  cudaGetSymbolAddress((void**)&gqkvl, g_qkvl);
    cudaGetSymbolAddress((void**)&gath,  g_ath);
    cudaGetSymbolAddress((void**)&gproj, g_proj);
    cudaGetSymbolAddress((void**)&ga,    g_a);
    cudaGetSymbolAddress((void**)&gah,   g_ah);
    cudaGetSymbolAddress((void**)&gh1h,  g_h1h);
    cudaGetSymbolAddress((void**)&gffn,  g_ffn);

    cudaFuncSetAttribute(gemm_tc, cudaFuncAttributeMaxDynamicSharedMemorySize, GEMM_SMEM);
    cudaFuncSetAttribute(flash_attn_tc, cudaFuncAttributeMaxDynamicSharedMemorySize, FA_SMEM);

    auto launch_gemm = [&](const fp16* Ah, const fp16* Bh, const fp16* Bl,
                           const float* bias, float* Cf, fp16* Ch, fp16* Cl,
                           int M, int N, int K, int relu) {
        dim3 grid(N / TBN, M / TBM);
        gemm_tc<<<grid, 256, GEMM_SMEM>>>(
            (const uint4*)Ah, (const uint4*)Bh, (const uint4*)Bl,
            bias, Cf, Ch, Cl, M, N, K, relu);
    };

    dim3 tb(32, 8);
    const int n4 = NTOK * Dm / 4;

    // 1: x = x_enc + x_pos
    add_convert<<<n4 / 256, 256>>>(x_enc, x_pos, gx, gxh, n4);
    // 2-4: QKV weights into fused buffer
    wconvert_t<<<dim3(Dm/32, Dm/32), tb>>>(wq, wqkvh,                   wqkvl,                   Dm, Dm);
    wconvert_t<<<dim3(Dm/32, Dm/32), tb>>>(wk, wqkvh + (size_t)Dm*Dm,   wqkvl + (size_t)Dm*Dm,   Dm, Dm);
    wconvert_t<<<dim3(Dm/32, Dm/32), tb>>>(wv, wqkvh + (size_t)2*Dm*Dm, wqkvl + (size_t)2*Dm*Dm, Dm, Dm);
    // 5: fused bias
    concat_bias<<<(NQKV + 255) / 256, 256>>>(bq, bk, bv, gbqkv);
    // 6: fused QKV GEMM
    launch_gemm(gxh, wqkvh, wqkvl, gbqkv, nullptr, gqkvh, gqkvl, NTOK, NQKV, Dm, 0);
    // 7: flash attention (cp.async double-buffered KV)
    flash_attn_tc<<<dim3(Sq / 128, Bsz * Hh), 256, FA_SMEM>>>(
        (const uint4*)gqkvh, (const uint4*)gqkvl, gath);
    // 8: wc convert, 9: output projection
    wconvert_t<<<dim3(Dm/32, Dm/32), tb>>>(wc, wch, wcl, Dm, Dm);
    launch_gemm(gath, wch, wcl, bc, gproj, nullptr, nullptr, NTOK, Dm, Dm, 0);
    // 10: a = x + LN(proj)
    ln_residual_kernel<<<NTOK, 256>>>(gx, gproj, g1, be1, ga, gah);
    // 11-12: FFN weights
    wconvert_t<<<dim3(Ff/32, Dm/32), tb>>>(w1, w1h, w1l, Dm, Ff);
    wconvert_t<<<dim3(Dm/32, Ff/32), tb>>>(w2, w2h, w2l, Ff, Dm);
    // 13-14: FFN
    launch_gemm(gah, w1h, w1l, b1, nullptr, gh1h, nullptr, NTOK, Ff, Dm, 1);
    launch_gemm(gh1h, w2h, w2l, b2, gffn, nullptr, nullptr, NTOK, Dm, Ff, 0);
    // 15: out = a + LN(ffn)
    ln_residual_kernel<<<NTOK, 256>>>(ga, gffn, g2, be2, out, nullptr);
}

// round 7
// speedup vs baseline: 3.7276x; 1.0240x over previous
#include <cuda_runtime.h>
#include <cuda_fp16.h>
#include <cstdint>
#include <math.h>

#define Bsz 2
#define Sq 2048
#define Dm 1024
#define Hh 16
#define DHd 64
#define Ff 4096
#define NTOK (Bsz*Sq)
#define NQKV 3072

typedef __half fp16;

// ---------------- scratch (device globals) ------------------------------------
__device__ float g_x[(size_t)NTOK*Dm];
__device__ fp16  g_xh[(size_t)NTOK*Dm];

__device__ fp16 g_wqkvh[(size_t)NQKV*Dm], g_wqkvl[(size_t)NQKV*Dm]; // [N=3K,K=D]
__device__ fp16 g_wch[(size_t)Dm*Dm], g_wcl[(size_t)Dm*Dm];
__device__ fp16 g_w1h[(size_t)Ff*Dm], g_w1l[(size_t)Ff*Dm];
__device__ fp16 g_w2h[(size_t)Dm*Ff], g_w2l[(size_t)Dm*Ff];
__device__ float g_bqkv[NQKV];

__device__ fp16 g_qkvh[(size_t)NTOK*NQKV], g_qkvl[(size_t)NTOK*NQKV];
__device__ fp16 g_ath[(size_t)NTOK*Dm];
__device__ float g_proj[(size_t)NTOK*Dm];
__device__ float g_a[(size_t)NTOK*Dm];
__device__ fp16  g_ah[(size_t)NTOK*Dm];
__device__ fp16  g_h1h[(size_t)NTOK*Ff];
__device__ float g_ffn[(size_t)NTOK*Dm];

// ---------------- helpers -------------------------------------------------------
__device__ __forceinline__ uint32_t smem_u32(const void* p){
    uint32_t a;
    asm("{ .reg .u64 t; cvta.to.shared.u64 t, %1; cvt.u32.u64 %0, t; }" : "=r"(a) : "l"(p));
    return a;
}
#define SWZ(x) ((x) ^ (((x) >> 3) & 0x70))

__device__ __forceinline__ void split2h(float v, fp16& h, fp16& l){
    h = __float2half_rn(v);
    l = __float2half_rn(v - __half2float(h));
}
__device__ __forceinline__ uint32_t pack_h2(float a, float b){
    __half2 t = __floats2half2_rn(a, b);
    return *(uint32_t*)&t;
}
__device__ __forceinline__ void cp16(uint32_t dst, const void* src){
    asm volatile("cp.async.cg.shared.global [%0], [%1], 16;" :: "r"(dst), "l"(src));
}
__device__ __forceinline__ void cp_commit(){
    asm volatile("cp.async.commit_group;" ::: "memory");
}
__device__ __forceinline__ void cp_wait1(){
    asm volatile("cp.async.wait_group 1;" ::: "memory");
}
__device__ __forceinline__ void cp_wait2(){
    asm volatile("cp.async.wait_group 2;" ::: "memory");
}

__device__ __forceinline__ void ldsm_x4(uint32_t& r0, uint32_t& r1, uint32_t& r2,
                                        uint32_t& r3, uint32_t addr){
    asm volatile("ldmatrix.sync.aligned.m8n8.x4.shared.b16 {%0,%1,%2,%3}, [%4];"
                 : "=r"(r0), "=r"(r1), "=r"(r2), "=r"(r3) : "r"(addr));
}
__device__ __forceinline__ void ldsm_x4_t(uint32_t& r0, uint32_t& r1, uint32_t& r2,
                                          uint32_t& r3, uint32_t addr){
    asm volatile("ldmatrix.sync.aligned.m8n8.x4.trans.shared.b16 {%0,%1,%2,%3}, [%4];"
                 : "=r"(r0), "=r"(r1), "=r"(r2), "=r"(r3) : "r"(addr));
}
__device__ __forceinline__ void mma16816(float* c, const uint32_t* a, const uint32_t* b){
    asm volatile(
        "mma.sync.aligned.m16n8k16.row.col.f32.f16.f16.f32 "
        "{%0,%1,%2,%3}, {%4,%5,%6,%7}, {%8,%9}, {%0,%1,%2,%3};"
        : "+f"(c[0]), "+f"(c[1]), "+f"(c[2]), "+f"(c[3])
        : "r"(a[0]), "r"(a[1]), "r"(a[2]), "r"(a[3]), "r"(b[0]), "r"(b[1]));
}

// FMA-pipe 2^t (avoids MUFU bottleneck)
__device__ __forceinline__ float exp2p(float t){
    t = fmaxf(t, -100.f);
    float n = t + 12582912.f;
    n -= 12582912.f;
    float f = t - n;
    float fl = f * 0.6931471805599453f;
    float p = fmaf(fl, fmaf(fl, fmaf(fl, fmaf(fl, fmaf(fl, 0.0083333333f,
              0.0416666667f), 0.1666666667f), 0.5f), 1.f), 1.f);
    return __uint_as_float((uint32_t)((int)n + 127) << 23) * p;
}

// ---------------- small prep kernels --------------------------------------------
__global__ void concat_bias(const float* __restrict__ a, const float* __restrict__ b,
                            const float* __restrict__ c, float* __restrict__ o)
{
    int i = blockIdx.x * 256 + threadIdx.x;
    if (i >= NQKV) return;
    o[i] = (i < 1024) ? a[i] : (i < 2048 ? b[i - 1024] : c[i - 2048]);
}

__global__ __launch_bounds__(256) void add_convert(
    const float* __restrict__ a, const float* __restrict__ b,
    float* __restrict__ o, fp16* __restrict__ oh, int n4)
{
    int i = blockIdx.x * 256 + threadIdx.x;
    if (i >= n4) return;
    float4 av = ((const float4*)a)[i];
    float4 bv = ((const float4*)b)[i];
    float4 v;
    v.x = av.x + bv.x; v.y = av.y + bv.y; v.z = av.z + bv.z; v.w = av.w + bv.w;
    ((float4*)o)[i] = v;
    uint32_t h[2] = { pack_h2(v.x, v.y), pack_h2(v.z, v.w) };
    *(uint2*)(oh + (size_t)i * 4) = *(uint2*)h;
}

// fused QKV weight transpose+split: one kernel, blockIdx.z selects W
__global__ __launch_bounds__(256) void wconvert_qkv(
    const float* __restrict__ wq, const float* __restrict__ wk,
    const float* __restrict__ wv, fp16* __restrict__ Th, fp16* __restrict__ Tl)
{
    __shared__ float t[32][33];
    const float* W = (blockIdx.z == 0) ? wq : (blockIdx.z == 1 ? wk : wv);
    const size_t zoff = (size_t)blockIdx.z * Dm * Dm;
    int n0 = blockIdx.x * 32, k0 = blockIdx.y * 32;
    int x = threadIdx.x, y = threadIdx.y;
    #pragma unroll
    for (int i = 0; i < 4; i++)
        t[y + 8*i][x] = W[(size_t)(k0 + y + 8*i) * Dm + n0 + x];
    __syncthreads();
    #pragma unroll
    for (int i = 0; i < 4; i++) {
        float v = t[x][y + 8*i];
        fp16 h, l; split2h(v, h, l);
        size_t idx = zoff + (size_t)(n0 + y + 8*i) * Dm + k0 + x;
        Th[idx] = h; Tl[idx] = l;
    }
}

__global__ __launch_bounds__(256) void wconvert_t(
    const float* __restrict__ W, fp16* __restrict__ Th, fp16* __restrict__ Tl,
    int K, int N)
{
    __shared__ float t[32][33];
    int n0 = blockIdx.x * 32, k0 = blockIdx.y * 32;
    int x = threadIdx.x, y = threadIdx.y;
    #pragma unroll
    for (int i = 0; i < 4; i++)
        t[y + 8*i][x] = W[(size_t)(k0 + y + 8*i) * N + n0 + x];
    __syncthreads();
    #pragma unroll
    for (int i = 0; i < 4; i++) {
        float v = t[x][y + 8*i];
        fp16 h, l; split2h(v, h, l);
        size_t idx = (size_t)(n0 + y + 8*i) * K + k0 + x;
        Th[idx] = h; Tl[idx] = l;
    }
}

// ---------------- fp16x2 GEMM: C = Ah[M,K] @ (Bh+Bl)[N,K]^T + bias --------------
#define TBM 128
#define TBN 256
#define STAGE 81920
#define GEMM_SMEM (2*STAGE)

__global__ __launch_bounds__(256, 1) void gemm_tc(
    const uint4* __restrict__ Ah4,
    const uint4* __restrict__ Bh4, const uint4* __restrict__ Bl4,
    const float* __restrict__ bias,
    float* __restrict__ Cf, fp16* __restrict__ Ch, fp16* __restrict__ Cl,
    int M, int N, int K, int relu, int loCol)
{
    extern __shared__ char smbuf[];
    const int tid = threadIdx.x;
    const int wid = tid >> 5;
    const int lane = tid & 31;
    const uint32_t sbase = smem_u32(smbuf);

    const int rowBase = blockIdx.y * TBM;
    const int colBase = blockIdx.x * TBN;
    const int K8 = K >> 3;
    const int nch = K >> 6;
    const int wm = (wid >> 2) * 64;
    const int wn = (wid & 3) * 64;

    auto issue_stage = [&](int chunk, int buf){
        uint32_t st = sbase + buf * STAGE;
        const int kc8 = chunk * 8;
        #pragma unroll
        for (int t = 0; t < 4; t++) {
            int id = tid + t * 256;
            int r = id >> 3, c = id & 7;
            cp16(st + SWZ(r * 128 + c * 16),
                 Ah4 + (size_t)(rowBase + r) * K8 + kc8 + c);
        }
        #pragma unroll
        for (int t = 0; t < 8; t++) {
            int id = tid + t * 256;
            int r = id >> 3, c = id & 7;
            uint32_t sw = SWZ(r * 128 + c * 16);
            size_t go = (size_t)(colBase + r) * K8 + kc8 + c;
            cp16(st + 16384 + sw, Bh4 + go);
            cp16(st + 49152 + sw, Bl4 + go);
        }
        cp_commit();
    };

    float acc[4][8][4];
    #pragma unroll
    for (int mt = 0; mt < 4; mt++)
        #pragma unroll
        for (int nt = 0; nt < 8; nt++)
            #pragma unroll
            for (int e = 0; e < 4; e++) acc[mt][nt][e] = 0.f;

    issue_stage(0, 0);
    issue_stage(1, 1);

    for (int i = 0; i < nch; i++) {
        cp_wait1();
        __syncthreads();
        const int buf = i & 1;
        const uint32_t ab = sbase + buf * STAGE;

        #pragma unroll
        for (int ks = 0; ks < 4; ks++) {
            const int kb = ks * 32;
            uint32_t af[4][4], bhf[4][4], blf[4][4];
            #pragma unroll
            for (int mt = 0; mt < 4; mt++) {
                uint32_t off = SWZ((wm + mt*16 + (lane & 15)) * 128 + kb + (lane >> 4) * 16);
                ldsm_x4(af[mt][0], af[mt][1], af[mt][2], af[mt][3], ab + off);
            }
            #pragma unroll
            for (int p = 0; p < 4; p++) {
                uint32_t off = SWZ((wn + p*16 + (lane & 15)) * 128 + kb + (lane >> 4) * 16);
                ldsm_x4(bhf[p][0], bhf[p][1], bhf[p][2], bhf[p][3], ab + 16384 + off);
                ldsm_x4(blf[p][0], blf[p][1], blf[p][2], blf[p][3], ab + 49152 + off);
            }
            // hi pass then lo pass: 32-op reuse distance per accumulator
            #pragma unroll
            for (int mt = 0; mt < 4; mt++) {
                #pragma unroll
                for (int nt = 0; nt < 8; nt++) {
                    const int p = nt >> 1, q = nt & 1;
                    uint32_t bh2[2] = { bhf[p][q], bhf[p][q + 2] };
                    mma16816(acc[mt][nt], af[mt], bh2);
                }
            }
            #pragma unroll
            for (int mt = 0; mt < 4; mt++) {
                #pragma unroll
                for (int nt = 0; nt < 8; nt++) {
                    const int p = nt >> 1, q = nt & 1;
                    uint32_t bl2[2] = { blf[p][q], blf[p][q + 2] };
                    mma16816(acc[mt][nt], af[mt], bl2);
                }
            }
        }
        __syncthreads();
        if (i + 2 < nch) issue_stage(i + 2, buf);
        else cp_commit();
    }

    #pragma unroll
    for (int mt = 0; mt < 4; mt++) {
        #pragma unroll
        for (int nt = 0; nt < 8; nt++) {
            int r0 = rowBase + wm + mt*16 + (lane >> 2);
            int c0 = colBase + wn + nt*8 + (lane & 3) * 2;
            float2 bb = *(const float2*)(bias + c0);
            #pragma unroll
            for (int half = 0; half < 2; half++) {
                int r = r0 + half * 8;
                float vx = acc[mt][nt][half*2 + 0] + bb.x;
                float vy = acc[mt][nt][half*2 + 1] + bb.y;
                if (relu) { vx = fmaxf(vx, 0.f); vy = fmaxf(vy, 0.f); }
                if (Cf) {
                    float2 o2 = {vx, vy};
                    *(float2*)(Cf + (size_t)r * N + c0) = o2;
                }
                if (Ch) {
                    uint32_t hp = pack_h2(vx, vy);
                    *(uint32_t*)(Ch + (size_t)r * N + c0) = hp;
                    if (Cl && c0 >= loCol) {
                        __half2 hh = *(__half2*)&hp;
                        uint32_t lp = pack_h2(vx - __half2float(hh.x),
                                              vy - __half2float(hh.y));
                        *(uint32_t*)(Cl + (size_t)r * N + c0) = lp;
                    }
                }
            }
        }
    }
}

// ---------------- tensor-core flash attention (fp16 2-pass, 3-stage cp.async) ---
// smem: Qh @0 (16K); stage s in {0,1,2}: Kh,Kl,Vh,Vl @ 16K + s*64K. Total 208K.
#define FA_STAGE 65536
#define FA_SMEM (16384 + 3*FA_STAGE)
#define QKV_P4 384
#define L2S 0.1803368801111f   // 0.125 * log2(e)

__global__ __launch_bounds__(256, 1) void flash_attn_tc(
    const uint4* __restrict__ qkvh, const uint4* __restrict__ qkvl,
    fp16* __restrict__ Oh)
{
    extern __shared__ char sm[];
    const uint32_t sb = smem_u32(sm);
    const int tid = threadIdx.x;
    const int wid = tid >> 5;
    const int lane = tid & 31;
    const int bh = blockIdx.y;
    const int b = bh >> 4, h = bh & 15;
    const int q0 = blockIdx.x * 128;

    auto issue_kv = [&](int j0, int buf){
        uint32_t st = sb + 16384 + buf * FA_STAGE;
        #pragma unroll
        for (int t = 0; t < 4; t++) {
            int id = tid + t * 256;
            int r = id >> 3, c = id & 7;
            size_t rowOff = (size_t)(b * Sq + j0 + r) * QKV_P4 + h * 8 + c;
            uint32_t sw = SWZ(r * 128 + c * 16);
            cp16(st +         sw, qkvh + rowOff + 128);  // Kh
            cp16(st + 16384 + sw, qkvl + rowOff + 128);  // Kl
            cp16(st + 32768 + sw, qkvh + rowOff + 256);  // Vh
            cp16(st + 49152 + sw, qkvl + rowOff + 256);  // Vl
        }
        cp_commit();
    };

    // load Q hi (sync; once)
    #pragma unroll
    for (int t = 0; t < 4; t++) {
        int id = tid + t * 256;
        int r = id >> 3, c = id & 7;
        size_t src = (size_t)(b * Sq + q0 + r) * QKV_P4 + h * 8 + c;
        *(uint4*)(sm + SWZ(r * 128 + c * 16)) = qkvh[src];
    }
    issue_kv(0, 0);
    issue_kv(128, 1);
    issue_kv(256, 2);
    __syncthreads();

    uint32_t qh[4][4];
    #pragma unroll
    for (int ks = 0; ks < 4; ks++) {
        uint32_t loc = SWZ((wid * 16 + (lane & 15)) * 128 + ks * 32 + (lane >> 4) * 16);
        ldsm_x4(qh[ks][0], qh[ks][1], qh[ks][2], qh[ks][3], sb + loc);
    }

    float o[8][4];
    #pragma unroll
    for (int u = 0; u < 8; u++)
        #pragma unroll
        for (int e = 0; e < 4; e++) o[u][e] = 0.f;
    float m0 = -1e30f, m1 = -1e30f, l0 = 0.f, l1 = 0.f;

    int buf = 0;
    for (int j0 = 0; j0 < Sq; j0 += 128) {
        cp_wait2();
        __syncthreads();
        const uint32_t kb = sb + 16384 + buf * FA_STAGE;

        // S = QK^T (2-pass fp16)
        float s[16][4];
        #pragma unroll
        for (int t = 0; t < 16; t++)
            #pragma unroll
            for (int e = 0; e < 4; e++) s[t][e] = 0.f;

        #pragma unroll
        for (int nc = 0; nc < 8; nc++) {
            #pragma unroll
            for (int ks = 0; ks < 4; ks++) {
                uint32_t kh[4], kl[4];
                uint32_t loc = SWZ((nc * 16 + (lane & 15)) * 128 + ks * 32 + (lane >> 4) * 16);
                ldsm_x4(kh[0], kh[1], kh[2], kh[3], kb + loc);
                ldsm_x4(kl[0], kl[1], kl[2], kl[3], kb + 16384 + loc);
                uint32_t bh0[2] = {kh[0], kh[2]}, bh1[2] = {kh[1], kh[3]};
                uint32_t bl0[2] = {kl[0], kl[2]}, bl1[2] = {kl[1], kl[3]};
                mma16816(s[2*nc],   qh[ks], bh0);
                mma16816(s[2*nc+1], qh[ks], bh1);
                mma16816(s[2*nc],   qh[ks], bl0);
                mma16816(s[2*nc+1], qh[ks], bl1);
            }
        }

        // online softmax
        float mx0 = -1e30f, mx1 = -1e30f;
        #pragma unroll
        for (int t = 0; t < 16; t++) {
            mx0 = fmaxf(mx0, fmaxf(s[t][0], s[t][1]));
            mx1 = fmaxf(mx1, fmaxf(s[t][2], s[t][3]));
        }
        mx0 = fmaxf(mx0, __shfl_xor_sync(0xffffffffu, mx0, 1));
        mx0 = fmaxf(mx0, __shfl_xor_sync(0xffffffffu, mx0, 2));
        mx1 = fmaxf(mx1, __shfl_xor_sync(0xffffffffu, mx1, 1));
        mx1 = fmaxf(mx1, __shfl_xor_sync(0xffffffffu, mx1, 2));
        float mn0 = fmaxf(m0, mx0), mn1 = fmaxf(m1, mx1);
        float c0 = exp2p((m0 - mn0) * L2S);
        float c1 = exp2p((m1 - mn1) * L2S);
        m0 = mn0; m1 = mn1;

        float sum0 = 0.f, sum1 = 0.f;
        uint32_t pA[16], pB[16];
        #pragma unroll
        for (int t = 0; t < 16; t++) {
            float p0 = exp2p((s[t][0] - mn0) * L2S);
            float p1 = exp2p((s[t][1] - mn0) * L2S);
            float p2 = exp2p((s[t][2] - mn1) * L2S);
            float p3 = exp2p((s[t][3] - mn1) * L2S);
            sum0 += p0 + p1;
            sum1 += p2 + p3;
            pA[t] = pack_h2(p0, p1);
            pB[t] = pack_h2(p2, p3);
        }
        sum0 += __shfl_xor_sync(0xffffffffu, sum0, 1);
        sum0 += __shfl_xor_sync(0xffffffffu, sum0, 2);
        sum1 += __shfl_xor_sync(0xffffffffu, sum1, 1);
        sum1 += __shfl_xor_sync(0xffffffffu, sum1, 2);
        l0 = l0 * c0 + sum0;
        l1 = l1 * c1 + sum1;
        #pragma unroll
        for (int u = 0; u < 8; u++) {
            o[u][0] *= c0; o[u][1] *= c0;
            o[u][2] *= c1; o[u][3] *= c1;
        }

        // O += P @ V (2-pass fp16: Ph*Vh + Ph*Vl)
        #pragma unroll
        for (int j = 0; j < 8; j++) {
            uint32_t ah[4] = {pA[2*j], pB[2*j], pA[2*j+1], pB[2*j+1]};
            #pragma unroll
            for (int p = 0; p < 4; p++) {
                uint32_t vh[4], vl[4];
                uint32_t loc = SWZ((j * 16 + (lane & 15)) * 128 + p * 32 + (lane >> 4) * 16);
                ldsm_x4_t(vh[0], vh[1], vh[2], vh[3], kb + 32768 + loc);
                ldsm_x4_t(vl[0], vl[1], vl[2], vl[3], kb + 49152 + loc);
                uint32_t bh0[2] = {vh[0], vh[1]}, bh1[2] = {vh[2], vh[3]};
                uint32_t bl0[2] = {vl[0], vl[1]}, bl1[2] = {vl[2], vl[3]};
                mma16816(o[2*p],   ah, bh0);
                mma16816(o[2*p+1], ah, bh1);
                mma16816(o[2*p],   ah, bl0);
                mma16816(o[2*p+1], ah, bl1);
            }
        }

        __syncthreads();
        if (j0 + 384 < Sq) issue_kv(j0 + 384, buf);
        else cp_commit();
        buf = (buf == 2) ? 0 : buf + 1;
    }

    float inv0 = 1.f / l0, inv1 = 1.f / l1;
    int r0 = q0 + wid * 16 + (lane >> 2);
    int r1 = r0 + 8;
    #pragma unroll
    for (int u = 0; u < 8; u++) {
        int col = h * 64 + u * 8 + (lane & 3) * 2;
        *(uint32_t*)(Oh + (size_t)(b * Sq + r0) * Dm + col) =
            pack_h2(o[u][0] * inv0, o[u][1] * inv0);
        *(uint32_t*)(Oh + (size_t)(b * Sq + r1) * Dm + col) =
            pack_h2(o[u][2] * inv1, o[u][3] * inv1);
    }
}

// ---------------- LayerNorm + residual -------------------------------------------
__global__ __launch_bounds__(256) void ln_residual_kernel(
    const float* __restrict__ res, const float* __restrict__ x,
    const float* __restrict__ g, const float* __restrict__ be,
    float* __restrict__ out, fp16* __restrict__ oh)
{
    const int row = blockIdx.x;
    const int tid = threadIdx.x;
    const float* xr = x + (size_t)row * Dm;

    float4 v = *(const float4*)(xr + tid * 4);
    float s1 = v.x + v.y + v.z + v.w;
    float s2 = v.x * v.x + v.y * v.y + v.z * v.z + v.w * v.w;
    #pragma unroll
    for (int off = 16; off; off >>= 1) {
        s1 += __shfl_xor_sync(0xffffffffu, s1, off);
        s2 += __shfl_xor_sync(0xffffffffu, s2, off);
    }
    __shared__ float r1[8], r2[8];
    if ((tid & 31) == 0) { r1[tid >> 5] = s1; r2[tid >> 5] = s2; }
    __syncthreads();
    float t1 = 0.f, t2 = 0.f;
    #pragma unroll
    for (int w = 0; w < 8; w++) { t1 += r1[w]; t2 += r2[w]; }

    const float mu  = t1 * (1.f / Dm);
    const float var = t2 * (1.f / Dm) - mu * mu;
    const float rstd = rsqrtf(var + 1e-6f);

    float4 rv = *(const float4*)(res + (size_t)row * Dm + tid * 4);
    float4 gv = *(const float4*)(g + tid * 4);
    float4 bv = *(const float4*)(be + tid * 4);
    float4 ov;
    ov.x = rv.x + (v.x - mu) * rstd * gv.x + bv.x;
    ov.y = rv.y + (v.y - mu) * rstd * gv.y + bv.y;
    ov.z = rv.z + (v.z - mu) * rstd * gv.z + bv.z;
    ov.w = rv.w + (v.w - mu) * rstd * gv.w + bv.w;
    *(float4*)(out + (size_t)row * Dm + tid * 4) = ov;
    if (oh) {
        uint32_t h2[2] = { pack_h2(ov.x, ov.y), pack_h2(ov.z, ov.w) };
        *(uint2*)(oh + (size_t)row * Dm + tid * 4) = *(uint2*)h2;
    }
}

// ---------------- launch ----------------------------------------------------------
extern "C" void kernel_launch(void* const* d_in, const int* in_sizes, int n_in,
                              void* d_out, int out_size)
{
    const float* x_enc = (const float*)d_in[0];
    const float* x_pos = (const float*)d_in[1];
    const float* wq = (const float*)d_in[2];  const float* bq = (const float*)d_in[3];
    const float* wk = (const float*)d_in[4];  const float* bk = (const float*)d_in[5];
    const float* wv = (const float*)d_in[6];  const float* bv = (const float*)d_in[7];
    const float* wc = (const float*)d_in[8];  const float* bc = (const float*)d_in[9];
    const float* w1 = (const float*)d_in[10]; const float* b1 = (const float*)d_in[11];
    const float* w2 = (const float*)d_in[12]; const float* b2 = (const float*)d_in[13];
    const float* g1 = (const float*)d_in[14]; const float* be1 = (const float*)d_in[15];
    const float* g2 = (const float*)d_in[16]; const float* be2 = (const float*)d_in[17];
    float* out = (float*)d_out;

    float *gx, *gproj, *ga, *gffn, *gbqkv;
    fp16 *gxh, *gath, *gah, *gh1h;
    fp16 *wqkvh, *wqkvl, *wch, *wcl, *w1h, *w1l, *w2h, *w2l, *gqkvh, *gqkvl;
    cudaGetSymbolAddress((void**)&gx,    g_x);
    cudaGetSymbolAddress((void**)&gxh,   g_xh);
    cudaGetSymbolAddress((void**)&wqkvh, g_wqkvh); cudaGetSymbolAddress((void**)&wqkvl, g_wqkvl);
    cudaGetSymbolAddress((void**)&wch,   g_wch);   cudaGetSymbolAddress((void**)&wcl,   g_wcl);
    cudaGetSymbolAddress((void**)&w1h,   g_w1h);   cudaGetSymbolAddress((void**)&w1l,   g_w1l);
    cudaGetSymbolAddress((void**)&w2h,   g_w2h);   cudaGetSymbolAddress((void**)&w2l,   g_w2l);
    cudaGetSymbolAddress((void**)&gbqkv, g_bqkv);
    cudaGetSymbolAddress((void**)&gqkvh, g_qkvh);  cudaGetSymbolAddress((void**)&gqkvl, g_qkvl);
    cudaGetSymbolAddress((void**)&gath,  g_ath);
    cudaGetSymbolAddress((void**)&gproj, g_proj);
    cudaGetSymbolAddress((void**)&ga,    g_a);
    cudaGetSymbolAddress((void**)&gah,   g_ah);
    cudaGetSymbolAddress((void**)&gh1h,  g_h1h);
    cudaGetSymbolAddress((void**)&gffn,  g_ffn);

    cudaFuncSetAttribute(gemm_tc, cudaFuncAttributeMaxDynamicSharedMemorySize, GEMM_SMEM);
    cudaFuncSetAttribute(flash_attn_tc, cudaFuncAttributeMaxDynamicSharedMemorySize, FA_SMEM);

    auto launch_gemm = [&](const fp16* Ah, const fp16* Bh, const fp16* Bl,
                           const float* bias, float* Cf, fp16* Ch, fp16* Cl,
                           int M, int N, int K, int relu, int loCol) {
        dim3 grid(N / TBN, M / TBM);
        gemm_tc<<<grid, 256, GEMM_SMEM>>>(
            (const uint4*)Ah, (const uint4*)Bh, (const uint4*)Bl,
            bias, Cf, Ch, Cl, M, N, K, relu, loCol);
    };

    dim3 tb(32, 8);
    const int n4 = NTOK * Dm / 4;

    // 1: fused QKV bias (no deps -> first)
    concat_bias<<<(NQKV + 255) / 256, 256>>>(bq, bk, bv, gbqkv);
    // 2: x = x_enc + x_pos
    add_convert<<<n4 / 256, 256>>>(x_enc, x_pos, gx, gxh, n4);
    // 3: fused QKV weight convert (one kernel, z = 3)
    wconvert_qkv<<<dim3(Dm/32, Dm/32, 3), tb>>>(wq, wk, wv, wqkvh, wqkvl);
    // 4: fused QKV GEMM (skip Q-lo epilogue writes: loCol=1024)
    launch_gemm(gxh, wqkvh, wqkvl, gbqkv, nullptr, gqkvh, gqkvl, NTOK, NQKV, Dm, 0, 1024);
    // 5: flash attention (3-stage cp.async KV pipeline)
    flash_attn_tc<<<dim3(Sq / 128, Bsz * Hh), 256, FA_SMEM>>>(
        (const uint4*)gqkvh, (const uint4*)gqkvl, gath);
    // 6: wc convert, 7: output projection
    wconvert_t<<<dim3(Dm/32, Dm/32), tb>>>(wc, wch, wcl, Dm, Dm);
    launch_gemm(gath, wch, wcl, bc, gproj, nullptr, nullptr, NTOK, Dm, Dm, 0, 0);
    // 8: a = x + LN(proj)
    ln_residual_kernel<<<NTOK, 256>>>(gx, gproj, g1, be1, ga, gah);
    // 9-10: FFN weights
    wconvert_t<<<dim3(Ff/32, Dm/32), tb>>>(w1, w1h, w1l, Dm, Ff);
    wconvert_t<<<dim3(Dm/32, Ff/32), tb>>>(w2, w2h, w2l, Ff, Dm);
    // 11-12: FFN
    launch_gemm(gah, w1h, w1l, b1, nullptr, gh1h, nullptr, NTOK, Ff, Dm, 1, 0);
    launch_gemm(gh1h, w2h, w2l, b2, gffn, nullptr, nullptr, NTOK, Dm, Ff, 0, 0);
    // 13: out = a + LN(ffn)
    ln_residual_kernel<<<NTOK, 256>>>(ga, gffn, g2, be2, out, nullptr);
}